// round 10
// baseline (speedup 1.0000x reference)
#include <cuda_runtime.h>
#include <math.h>

#define B    64
#define D    128
#define LC   1024
#define LQ   256
#define NEG_INF -1e30f
#define SA   136     // smem row stride (136%32==8 -> conflict-free fragment reads)
#define SB   72      // smem row stride for 64-wide tiles (72%32==8)

// ---------------- scratch (device globals: no allocation allowed) ----------------
__device__ float g_E[(size_t)B * LC * LQ];   // exp(S), 64 MiB
__device__ float g_M[(size_t)B * LQ * D];    // S2^T @ Ct (already / colsum)
__device__ float g_rowsum[B * LC];
__device__ float g_colsum[B * LQ];
__device__ float g_cw1[B * LC];
__device__ float g_qw2[B * LQ];
__device__ float g_fc[B * LC];               // exp((1-cmask)*NEG_INF)  (0 or 1)
__device__ float g_fq[B * LQ];               // exp((1-qmask)*NEG_INF)

// ---------------- tf32 helpers ----------------
__device__ __forceinline__ unsigned f2t(float x) {
    unsigned u; asm("cvt.rna.tf32.f32 %0, %1;" : "=r"(u) : "f"(x)); return u;
}
__device__ __forceinline__ uint4 f2t4(float4 v) {
    return make_uint4(f2t(v.x), f2t(v.y), f2t(v.z), f2t(v.w));
}
__device__ __forceinline__ void mma8(float* c, const unsigned* a, const unsigned* b) {
    asm volatile(
        "mma.sync.aligned.m16n8k8.row.col.f32.tf32.tf32.f32 "
        "{%0,%1,%2,%3},{%4,%5,%6,%7},{%8,%9},{%0,%1,%2,%3};"
        : "+f"(c[0]), "+f"(c[1]), "+f"(c[2]), "+f"(c[3])
        : "r"(a[0]), "r"(a[1]), "r"(a[2]), "r"(a[3]), "r"(b[0]), "r"(b[1]));
}

// ---------------- K0: biases, mask factors, zero accumulators ----------------
__global__ void k0_setup(const float* __restrict__ C, const float* __restrict__ Q,
                         const float* __restrict__ cmask, const float* __restrict__ qmask,
                         const float* __restrict__ w) {
    int idx = blockIdx.x * 256 + threadIdx.x;
    if (idx < B * LC) {
        int b = idx >> 10;
        int i = idx & (LC - 1);
        const float* cp = C + (size_t)b * D * LC + i;
        float s = 0.f;
#pragma unroll 4
        for (int dd = 0; dd < D; ++dd) s = fmaf(cp[(size_t)dd * LC], w[dd], s);
        g_cw1[idx] = s;
        g_fc[idx] = __expf((1.0f - cmask[idx]) * NEG_INF);
        g_rowsum[idx] = 0.f;
    } else {
        int t = idx - B * LC;
        if (t < B * LQ) {
            int b = t >> 8;
            int j = t & (LQ - 1);
            const float* qp = Q + (size_t)b * D * LQ + j;
            float s = 0.f;
#pragma unroll 4
            for (int dd = 0; dd < D; ++dd) s = fmaf(qp[(size_t)dd * LQ], w[D + dd], s);
            g_qw2[t] = s;
            g_fq[t] = __expf((1.0f - qmask[t]) * NEG_INF);
            g_colsum[t] = 0.f;
        }
    }
}

// ---------------- K1: E = exp(S) + row/col exp-sums (tf32 MMA) ---------------
// grid (LQ/128, LC/128, B), 256 thr.  M=i(128) N=j(128) K=d(128)
__global__ __launch_bounds__(256, 2) void k1_score(const float* __restrict__ C,
                                                   const float* __restrict__ Q,
                                                   const float* __restrict__ w) {
    int b = blockIdx.z, i0 = blockIdx.y * 128, j0 = blockIdx.x * 128;

    __shared__ __align__(16) unsigned SMB[2 * 32 * SA];   // As|Bs; reused as tr[64][SA]
    unsigned (*As)[SA] = (unsigned(*)[SA])SMB;
    unsigned (*Bs)[SA] = (unsigned(*)[SA])(SMB + 32 * SA);
    float* tr = (float*)SMB;
    __shared__ float scw[128], sfcs[128], sqw[128], sfqs[128], srow[128], scol[128];

    int tid = threadIdx.x;
    int wid = tid >> 5, lane = tid & 31, g = lane >> 2, t = lane & 3;
    int wm = wid & 3, wn = wid >> 2;     // warp tile: 32(m) x 64(n)

    float acc[2][8][4];
#pragma unroll
    for (int mt = 0; mt < 2; ++mt)
#pragma unroll
        for (int nt = 0; nt < 8; ++nt)
#pragma unroll
            for (int c = 0; c < 4; ++c) acc[mt][nt][c] = 0.f;

    const float* Cb = C + (size_t)b * D * LC;
    const float* Qb = Q + (size_t)b * D * LQ;

    int qm = tid & 31, kr = tid >> 5;    // loader: m-quad, k-row

    uint4 pa[4], pb[4];
#pragma unroll
    for (int p = 0; p < 4; ++p) {        // prefetch chunk 0
        int k = kr + 8 * p;
        float w3 = w[2 * D + k];
        float4 v = *(const float4*)(Cb + (size_t)k * LC + i0 + 4 * qm);
        v.x *= w3; v.y *= w3; v.z *= w3; v.w *= w3;
        pa[p] = f2t4(v);
        pb[p] = f2t4(*(const float4*)(Qb + (size_t)k * LQ + j0 + 4 * qm));
    }

    for (int kc = 0; kc < D; kc += 32) {
        __syncthreads();
#pragma unroll
        for (int p = 0; p < 4; ++p) {
            *(uint4*)&As[kr + 8 * p][4 * qm] = pa[p];
            *(uint4*)&Bs[kr + 8 * p][4 * qm] = pb[p];
        }
        __syncthreads();
        if (kc + 32 < D) {
#pragma unroll
            for (int p = 0; p < 4; ++p) {
                int k = kc + 32 + kr + 8 * p;
                float w3 = w[2 * D + k];
                float4 v = *(const float4*)(Cb + (size_t)k * LC + i0 + 4 * qm);
                v.x *= w3; v.y *= w3; v.z *= w3; v.w *= w3;
                pa[p] = f2t4(v);
                pb[p] = f2t4(*(const float4*)(Qb + (size_t)k * LQ + j0 + 4 * qm));
            }
        }
#pragma unroll
        for (int k8 = 0; k8 < 4; ++k8) {
            int kk = 8 * k8;
            unsigned a[2][4];
#pragma unroll
            for (int mt = 0; mt < 2; ++mt) {
                int R = wm * 32 + mt * 16 + g;
                a[mt][0] = As[kk + t][R];
                a[mt][1] = As[kk + t][R + 8];
                a[mt][2] = As[kk + t + 4][R];
                a[mt][3] = As[kk + t + 4][R + 8];
            }
#pragma unroll
            for (int nt = 0; nt < 8; ++nt) {
                int NN = wn * 64 + nt * 8 + g;
                unsigned bb[2] = { Bs[kk + t][NN], Bs[kk + t + 4][NN] };
#pragma unroll
                for (int mt = 0; mt < 2; ++mt) mma8(acc[mt][nt], a[mt], bb);
            }
        }
    }

    // ---- epilogue: exp into acc, row/col partial sums ----
    __syncthreads();
    if (tid < 128) {
        scw[tid]  = g_cw1[b * LC + i0 + tid];
        sfcs[tid] = g_fc[b * LC + i0 + tid];
        srow[tid] = 0.f;
    } else {
        int j = tid - 128;
        sqw[j]  = g_qw2[b * LQ + j0 + j];
        sfqs[j] = g_fq[b * LQ + j0 + j];
        scol[j] = 0.f;
    }
    __syncthreads();

    float rowp[4] = {0.f, 0.f, 0.f, 0.f};
    float colp[16];
#pragma unroll
    for (int c = 0; c < 16; ++c) colp[c] = 0.f;

#pragma unroll
    for (int mt = 0; mt < 2; ++mt)
#pragma unroll
        for (int half = 0; half < 2; ++half) {
            int rl = wm * 32 + mt * 16 + g + 8 * half;
            float cwv = scw[rl], fcv = sfcs[rl];
#pragma unroll
            for (int nt = 0; nt < 8; ++nt) {
                int cl = wn * 64 + nt * 8 + 2 * t;
                float e0 = __expf(acc[mt][nt][half * 2 + 0] + cwv + sqw[cl]);
                float e1 = __expf(acc[mt][nt][half * 2 + 1] + cwv + sqw[cl + 1]);
                acc[mt][nt][half * 2 + 0] = e0;
                acc[mt][nt][half * 2 + 1] = e1;
                rowp[mt * 2 + half] += e0 * sfqs[cl] + e1 * sfqs[cl + 1];
                colp[nt * 2 + 0] += e0 * fcv;
                colp[nt * 2 + 1] += e1 * fcv;
            }
        }

#pragma unroll
    for (int r = 0; r < 4; ++r) {
        rowp[r] += __shfl_xor_sync(0xffffffffu, rowp[r], 1);
        rowp[r] += __shfl_xor_sync(0xffffffffu, rowp[r], 2);
    }
    if (t == 0) {
#pragma unroll
        for (int mt = 0; mt < 2; ++mt)
#pragma unroll
            for (int half = 0; half < 2; ++half)
                atomicAdd(&srow[wm * 32 + mt * 16 + g + 8 * half], rowp[mt * 2 + half]);
    }
#pragma unroll
    for (int c = 0; c < 16; ++c) {
        colp[c] += __shfl_xor_sync(0xffffffffu, colp[c], 4);
        colp[c] += __shfl_xor_sync(0xffffffffu, colp[c], 8);
        colp[c] += __shfl_xor_sync(0xffffffffu, colp[c], 16);
    }
    if (g == 0) {
#pragma unroll
        for (int nt = 0; nt < 8; ++nt)
#pragma unroll
            for (int par = 0; par < 2; ++par)
                atomicAdd(&scol[wn * 64 + nt * 8 + 2 * t + par], colp[nt * 2 + par]);
    }
    __syncthreads();
    if (tid < 128) atomicAdd(&g_rowsum[b * LC + i0 + tid], srow[tid]);
    else           atomicAdd(&g_colsum[b * LQ + j0 + tid - 128], scol[tid - 128]);

    // ---- coalesced E store via smem transpose (2 chunks of 64 rows) ----
    int r2 = tid >> 4, c16 = tid & 15;
#pragma unroll
    for (int ch = 0; ch < 2; ++ch) {
        __syncthreads();
        if ((wm >> 1) == ch) {
#pragma unroll
            for (int mt = 0; mt < 2; ++mt)
#pragma unroll
                for (int half = 0; half < 2; ++half) {
                    int rowl = (wm & 1) * 32 + mt * 16 + g + 8 * half;
#pragma unroll
                    for (int nt = 0; nt < 8; ++nt) {
                        int col = wn * 64 + nt * 8 + 2 * t;
                        tr[rowl * SA + col]     = acc[mt][nt][half * 2 + 0];
                        tr[rowl * SA + col + 1] = acc[mt][nt][half * 2 + 1];
                    }
                }
        }
        __syncthreads();
        float* dst = g_E + ((size_t)b * LC + i0 + ch * 64) * LQ + j0;
#pragma unroll
        for (int rr = 0; rr < 4; ++rr)
#pragma unroll
            for (int seg = 0; seg < 2; ++seg) {
                int row = r2 + 16 * rr;
                *(float4*)(dst + (size_t)row * LQ + seg * 64 + 4 * c16) =
                    *(float4*)&tr[row * SA + seg * 64 + 4 * c16];
            }
    }
}

// ---------------- K4: M[j][dd] = (sum_i E[i][j]*fc[i]*C[dd][i]) / colsum[j] --
// grid (LQ/128, B), 256 thr.  M=j(128) N=dd(128) K=i(1024)
__global__ __launch_bounds__(256, 2) void k4_m(const float* __restrict__ C) {
    int b = blockIdx.y, j0 = blockIdx.x * 128;

    __shared__ __align__(16) unsigned SMB[2 * 32 * SA];
    unsigned (*As)[SA] = (unsigned(*)[SA])SMB;
    unsigned (*Bs)[SA] = (unsigned(*)[SA])(SMB + 32 * SA);
    float* tr = (float*)SMB;

    int tid = threadIdx.x;
    int wid = tid >> 5, lane = tid & 31, g = lane >> 2, t = lane & 3;
    int wm = wid & 3, wn = wid >> 2;

    float acc[2][8][4];
#pragma unroll
    for (int mt = 0; mt < 2; ++mt)
#pragma unroll
        for (int nt = 0; nt < 8; ++nt)
#pragma unroll
            for (int c = 0; c < 4; ++c) acc[mt][nt][c] = 0.f;

    const float* Cb = C + (size_t)b * D * LC;
    const float* Eb = g_E + (size_t)b * LC * LQ;

    int qm = tid & 31, kr = tid >> 5;     // A loader
    int dd = tid & 127, kq = tid >> 7;    // B loader (transpose)

    uint4 va[4], vb[4];
#pragma unroll
    for (int p = 0; p < 4; ++p) {
        int i = kr + 8 * p;
        float f = g_fc[b * LC + i];
        float4 v = *(const float4*)(Eb + (size_t)i * LQ + j0 + 4 * qm);
        v.x *= f; v.y *= f; v.z *= f; v.w *= f;
        va[p] = f2t4(v);
        vb[p] = f2t4(*(const float4*)(Cb + (size_t)dd * LC + 4 * (kq + 2 * p)));
    }

    for (int kc = 0; kc < LC; kc += 32) {
        __syncthreads();
#pragma unroll
        for (int p = 0; p < 4; ++p) {
            *(uint4*)&As[kr + 8 * p][4 * qm] = va[p];
            int kb = 4 * (kq + 2 * p);
            Bs[kb + 0][dd] = vb[p].x;
            Bs[kb + 1][dd] = vb[p].y;
            Bs[kb + 2][dd] = vb[p].z;
            Bs[kb + 3][dd] = vb[p].w;
        }
        __syncthreads();
        if (kc + 32 < LC) {
#pragma unroll
            for (int p = 0; p < 4; ++p) {
                int i = kc + 32 + kr + 8 * p;
                float f = g_fc[b * LC + i];
                float4 v = *(const float4*)(Eb + (size_t)i * LQ + j0 + 4 * qm);
                v.x *= f; v.y *= f; v.z *= f; v.w *= f;
                va[p] = f2t4(v);
                vb[p] = f2t4(*(const float4*)(Cb + (size_t)dd * LC + kc + 32 + 4 * (kq + 2 * p)));
            }
        }
#pragma unroll
        for (int k8 = 0; k8 < 4; ++k8) {
            int kk = 8 * k8;
            unsigned a[2][4];
#pragma unroll
            for (int mt = 0; mt < 2; ++mt) {
                int R = wm * 32 + mt * 16 + g;
                a[mt][0] = As[kk + t][R];
                a[mt][1] = As[kk + t][R + 8];
                a[mt][2] = As[kk + t + 4][R];
                a[mt][3] = As[kk + t + 4][R + 8];
            }
#pragma unroll
            for (int nt = 0; nt < 8; ++nt) {
                int NN = wn * 64 + nt * 8 + g;
                unsigned bb[2] = { Bs[kk + t][NN], Bs[kk + t + 4][NN] };
#pragma unroll
                for (int mt = 0; mt < 2; ++mt) mma8(acc[mt][nt], a[mt], bb);
            }
        }
    }

    // ---- coalesced M store via smem transpose (2 chunks of 64 j-rows) ----
    int r2 = tid >> 4, c16 = tid & 15;
#pragma unroll
    for (int ch = 0; ch < 2; ++ch) {
        __syncthreads();
        if ((wm >> 1) == ch) {
#pragma unroll
            for (int mt = 0; mt < 2; ++mt)
#pragma unroll
                for (int half = 0; half < 2; ++half) {
                    int rowl = (wm & 1) * 32 + mt * 16 + g + 8 * half;
                    float ci = 1.0f / g_colsum[b * LQ + j0 + ch * 64 + rowl];
#pragma unroll
                    for (int nt = 0; nt < 8; ++nt) {
                        int col = wn * 64 + nt * 8 + 2 * t;
                        tr[rowl * SA + col]     = acc[mt][nt][half * 2 + 0] * ci;
                        tr[rowl * SA + col + 1] = acc[mt][nt][half * 2 + 1] * ci;
                    }
                }
        }
        __syncthreads();
        float* dst = g_M + ((size_t)b * LQ + j0 + ch * 64) * D;
#pragma unroll
        for (int rr = 0; rr < 4; ++rr)
#pragma unroll
            for (int seg = 0; seg < 2; ++seg) {
                int row = r2 + 16 * rr;
                *(float4*)(dst + (size_t)row * D + seg * 64 + 4 * c16) =
                    *(float4*)&tr[row * SA + seg * 64 + 4 * c16];
            }
    }
}

// ---------------- K5: A & Bmat (dual GEMM) + 4 output channels ----------------
// grid (D/64, LC/128, B), 256 thr.  M=i(128) N=dd(64) K=j(256)
__global__ __launch_bounds__(256, 2) void k5_out(const float* __restrict__ C,
                                                 const float* __restrict__ Q,
                                                 float* __restrict__ out) {
    int b = blockIdx.z, i0 = blockIdx.y * 128, dd0 = blockIdx.x * 64;

    __shared__ __align__(16) unsigned SMB[32 * SA + 2 * 32 * SB];  // As|Bq|Bm; tr[64][SA]
    unsigned (*As)[SA] = (unsigned(*)[SA])SMB;
    unsigned (*Bq)[SB] = (unsigned(*)[SB])(SMB + 32 * SA);
    unsigned (*Bm)[SB] = (unsigned(*)[SB])(SMB + 32 * SA + 32 * SB);
    float* tr = (float*)SMB;
    __shared__ float sfq[LQ];

    int tid = threadIdx.x;
    int wid = tid >> 5, lane = tid & 31, g = lane >> 2, t = lane & 3;
    int wm = wid & 3, wn = wid >> 2;     // warp tile: 32(m) x 32(n)

    sfq[tid] = g_fq[b * LQ + tid];

    float accA[2][4][4], accB[2][4][4];
#pragma unroll
    for (int mt = 0; mt < 2; ++mt)
#pragma unroll
        for (int nt = 0; nt < 4; ++nt)
#pragma unroll
            for (int c = 0; c < 4; ++c) { accA[mt][nt][c] = 0.f; accB[mt][nt][c] = 0.f; }

    const float* Cb = C + (size_t)b * D * LC;
    const float* Qb = Q + (size_t)b * D * LQ;
    const float* Eb = g_E + (size_t)b * LC * LQ;
    const float* Mb = g_M + (size_t)b * LQ * D;

    int ia = tid & 127, kqa = tid >> 7;        // A loader (transpose)
    int dq = tid & 63,  kq2 = (tid >> 6) & 3;  // Bq loader (transpose)
    int qn = tid & 15,  krm = tid >> 4;        // Bm loader (direct)

    float4 ea[4];
    uint4 qa[2], ma[2];
#pragma unroll
    for (int p = 0; p < 4; ++p)
        ea[p] = *(const float4*)(Eb + (size_t)(i0 + ia) * LQ + 4 * (kqa + 2 * p));
#pragma unroll
    for (int p = 0; p < 2; ++p) {
        qa[p] = f2t4(*(const float4*)(Qb + (size_t)(dd0 + dq) * LQ + 4 * (kq2 + 4 * p)));
        ma[p] = f2t4(*(const float4*)(Mb + (size_t)(krm + 16 * p) * D + dd0 + 4 * qn));
    }

    for (int kc = 0; kc < LQ; kc += 32) {
        __syncthreads();
#pragma unroll
        for (int p = 0; p < 4; ++p) {
            int ka = 4 * (kqa + 2 * p);
            As[ka + 0][ia] = f2t(ea[p].x * sfq[kc + ka + 0]);
            As[ka + 1][ia] = f2t(ea[p].y * sfq[kc + ka + 1]);
            As[ka + 2][ia] = f2t(ea[p].z * sfq[kc + ka + 2]);
            As[ka + 3][ia] = f2t(ea[p].w * sfq[kc + ka + 3]);
        }
#pragma unroll
        for (int p = 0; p < 2; ++p) {
            int kb = 4 * (kq2 + 4 * p);
            Bq[kb + 0][dq] = qa[p].x;
            Bq[kb + 1][dq] = qa[p].y;
            Bq[kb + 2][dq] = qa[p].z;
            Bq[kb + 3][dq] = qa[p].w;
            *(uint4*)&Bm[krm + 16 * p][4 * qn] = ma[p];
        }
        __syncthreads();
        if (kc + 32 < LQ) {
#pragma unroll
            for (int p = 0; p < 4; ++p)
                ea[p] = *(const float4*)(Eb + (size_t)(i0 + ia) * LQ + kc + 32 + 4 * (kqa + 2 * p));
#pragma unroll
            for (int p = 0; p < 2; ++p) {
                qa[p] = f2t4(*(const float4*)(Qb + (size_t)(dd0 + dq) * LQ + kc + 32 + 4 * (kq2 + 4 * p)));
                ma[p] = f2t4(*(const float4*)(Mb + (size_t)(kc + 32 + krm + 16 * p) * D + dd0 + 4 * qn));
            }
        }
#pragma unroll
        for (int k8 = 0; k8 < 4; ++k8) {
            int kk = 8 * k8;
            unsigned a[2][4];
#pragma unroll
            for (int mt = 0; mt < 2; ++mt) {
                int R = wm * 32 + mt * 16 + g;
                a[mt][0] = As[kk + t][R];
                a[mt][1] = As[kk + t][R + 8];
                a[mt][2] = As[kk + t + 4][R];
                a[mt][3] = As[kk + t + 4][R + 8];
            }
#pragma unroll
            for (int nt = 0; nt < 4; ++nt) {
                int NN = wn * 32 + nt * 8 + g;
                unsigned bq[2] = { Bq[kk + t][NN], Bq[kk + t + 4][NN] };
                unsigned bm[2] = { Bm[kk + t][NN], Bm[kk + t + 4][NN] };
#pragma unroll
                for (int mt = 0; mt < 2; ++mt) {
                    mma8(accA[mt][nt], a[mt], bq);
                    mma8(accB[mt][nt], a[mt], bm);
                }
            }
        }
    }

    // ---- epilogue: rowsum scale, transpose in smem, coalesced stores ----
    float rinv[2][2];
#pragma unroll
    for (int mt = 0; mt < 2; ++mt)
#pragma unroll
        for (int half = 0; half < 2; ++half)
            rinv[mt][half] = 1.0f / g_rowsum[b * LC + i0 + wm * 32 + mt * 16 + g + 8 * half];

    int r2 = tid >> 4, c16 = tid & 15;
    size_t ob = (size_t)b * 4 * D * LC;
    const float* Csrc = Cb + (size_t)dd0 * LC + i0;
    float* o0 = out + ob + (size_t)dd0 * LC + i0;

    // phase A: channels 0 (Ct), 1 (A), 2 (Ct*A)
    __syncthreads();
#pragma unroll
    for (int mt = 0; mt < 2; ++mt)
#pragma unroll
        for (int half = 0; half < 2; ++half) {
            int iil = wm * 32 + mt * 16 + g + 8 * half;
#pragma unroll
            for (int nt = 0; nt < 4; ++nt) {
                int ddl = wn * 32 + nt * 8 + 2 * t;
                tr[ddl * SA + iil]       = accA[mt][nt][half * 2 + 0] * rinv[mt][half];
                tr[(ddl + 1) * SA + iil] = accA[mt][nt][half * 2 + 1] * rinv[mt][half];
            }
        }
    __syncthreads();
#pragma unroll
    for (int rr = 0; rr < 4; ++rr)
#pragma unroll
        for (int seg = 0; seg < 2; ++seg) {
            int row = r2 + 16 * rr;
            int off = seg * 64 + 4 * c16;
            float4 a4 = *(float4*)&tr[row * SA + off];
            float4 c4 = *(const float4*)(Csrc + (size_t)row * LC + off);
            size_t go = (size_t)row * LC + off;
            *(float4*)(o0 + go) = c4;
            *(float4*)(o0 + (size_t)D * LC + go) = a4;
            *(float4*)(o0 + (size_t)2 * D * LC + go) =
                make_float4(c4.x * a4.x, c4.y * a4.y, c4.z * a4.z, c4.w * a4.w);
        }

    // phase B: channel 3 (Ct*Bmat)
    __syncthreads();
#pragma unroll
    for (int mt = 0; mt < 2; ++mt)
#pragma unroll
        for (int half = 0; half < 2; ++half) {
            int iil = wm * 32 + mt * 16 + g + 8 * half;
#pragma unroll
            for (int nt = 0; nt < 4; ++nt) {
                int ddl = wn * 32 + nt * 8 + 2 * t;
                tr[ddl * SA + iil]       = accB[mt][nt][half * 2 + 0] * rinv[mt][half];
                tr[(ddl + 1) * SA + iil] = accB[mt][nt][half * 2 + 1] * rinv[mt][half];
            }
        }
    __syncthreads();
#pragma unroll
    for (int rr = 0; rr < 4; ++rr)
#pragma unroll
        for (int seg = 0; seg < 2; ++seg) {
            int row = r2 + 16 * rr;
            int off = seg * 64 + 4 * c16;
            float4 b4 = *(float4*)&tr[row * SA + off];
            float4 c4 = *(const float4*)(Csrc + (size_t)row * LC + off);
            *(float4*)(o0 + (size_t)3 * D * LC + (size_t)row * LC + off) =
                make_float4(c4.x * b4.x, c4.y * b4.y, c4.z * b4.z, c4.w * b4.w);
        }
}

// ---------------- launch ------------------------------------------------------
extern "C" void kernel_launch(void* const* d_in, const int* in_sizes, int n_in,
                              void* d_out, int out_size) {
    const float* C = (const float*)d_in[0];
    const float* Q = (const float*)d_in[1];
    const float* cmask = (const float*)d_in[2];
    const float* qmask = (const float*)d_in[3];
    const float* w = (const float*)d_in[4];
    float* out = (float*)d_out;

    k0_setup<<<(B * LC + B * LQ) / 256, 256>>>(C, Q, cmask, qmask, w);

    dim3 g1(LQ / 128, LC / 128, B);
    k1_score<<<g1, 256>>>(C, Q, w);

    dim3 g4(LQ / 128, B);
    k4_m<<<g4, 256>>>(C);

    dim3 g5(D / 64, LC / 128, B);
    k5_out<<<g5, 256>>>(C, Q, out);
}

// round 11
// speedup vs baseline: 1.0080x; 1.0080x over previous
#include <cuda_runtime.h>
#include <math.h>

#define B    64
#define D    128
#define LC   1024
#define LQ   256
#define NEG_INF -1e30f
#define SA   136     // smem row stride (136%32==8 -> conflict-free fragment reads)
#define SB   72      // smem row stride for 64-wide tiles (72%32==8)

// ---------------- scratch (device globals: no allocation allowed) ----------------
__device__ float g_E[(size_t)B * LC * LQ];   // exp(S), 64 MiB
__device__ float g_M[(size_t)B * LQ * D];    // S2^T @ Ct (already / colsum)
__device__ float g_rowsum[B * LC];
__device__ float g_colsum[B * LQ];
__device__ float g_cw1[B * LC];
__device__ float g_qw2[B * LQ];
__device__ float g_fc[B * LC];               // exp((1-cmask)*NEG_INF)  (0 or 1)
__device__ float g_fq[B * LQ];               // exp((1-qmask)*NEG_INF)

// ---------------- tf32 helpers ----------------
__device__ __forceinline__ unsigned f2t(float x) {
    unsigned u; asm("cvt.rna.tf32.f32 %0, %1;" : "=r"(u) : "f"(x)); return u;
}
__device__ __forceinline__ uint4 f2t4(float4 v) {
    return make_uint4(f2t(v.x), f2t(v.y), f2t(v.z), f2t(v.w));
}
__device__ __forceinline__ void mma8(float* c, const unsigned* a, const unsigned* b) {
    asm volatile(
        "mma.sync.aligned.m16n8k8.row.col.f32.tf32.tf32.f32 "
        "{%0,%1,%2,%3},{%4,%5,%6,%7},{%8,%9},{%0,%1,%2,%3};"
        : "+f"(c[0]), "+f"(c[1]), "+f"(c[2]), "+f"(c[3])
        : "r"(a[0]), "r"(a[1]), "r"(a[2]), "r"(a[3]), "r"(b[0]), "r"(b[1]));
}

// ---------------- K0: biases, mask factors, zero accumulators ----------------
__global__ void k0_setup(const float* __restrict__ C, const float* __restrict__ Q,
                         const float* __restrict__ cmask, const float* __restrict__ qmask,
                         const float* __restrict__ w) {
    int idx = blockIdx.x * 256 + threadIdx.x;
    if (idx < B * LC) {
        int b = idx >> 10;
        int i = idx & (LC - 1);
        const float* cp = C + (size_t)b * D * LC + i;
        float s = 0.f;
#pragma unroll 4
        for (int dd = 0; dd < D; ++dd) s = fmaf(cp[(size_t)dd * LC], w[dd], s);
        g_cw1[idx] = s;
        g_fc[idx] = __expf((1.0f - cmask[idx]) * NEG_INF);
        g_rowsum[idx] = 0.f;
    } else {
        int t = idx - B * LC;
        if (t < B * LQ) {
            int b = t >> 8;
            int j = t & (LQ - 1);
            const float* qp = Q + (size_t)b * D * LQ + j;
            float s = 0.f;
#pragma unroll 4
            for (int dd = 0; dd < D; ++dd) s = fmaf(qp[(size_t)dd * LQ], w[D + dd], s);
            g_qw2[t] = s;
            g_fq[t] = __expf((1.0f - qmask[t]) * NEG_INF);
            g_colsum[t] = 0.f;
        }
    }
}

// ---------------- K1: E = exp(S) + row/col exp-sums (tf32 MMA) ---------------
// grid (LQ/128, LC/128, B), 256 thr.  M=i(128) N=j(128) K=d(128)
__global__ __launch_bounds__(256, 2) void k1_score(const float* __restrict__ C,
                                                   const float* __restrict__ Q,
                                                   const float* __restrict__ w) {
    int b = blockIdx.z, i0 = blockIdx.y * 128, j0 = blockIdx.x * 128;

    __shared__ __align__(16) unsigned SMB[2 * 32 * SA];   // As|Bs; reused as tr[64][SA]
    unsigned (*As)[SA] = (unsigned(*)[SA])SMB;
    unsigned (*Bs)[SA] = (unsigned(*)[SA])(SMB + 32 * SA);
    float* tr = (float*)SMB;
    __shared__ float scw[128], sfcs[128], sqw[128], sfqs[128], srow[128], scol[128];

    int tid = threadIdx.x;
    int wid = tid >> 5, lane = tid & 31, g = lane >> 2, t = lane & 3;
    int wm = wid & 3, wn = wid >> 2;     // warp tile: 32(m) x 64(n)

    float acc[2][8][4];
#pragma unroll
    for (int mt = 0; mt < 2; ++mt)
#pragma unroll
        for (int nt = 0; nt < 8; ++nt)
#pragma unroll
            for (int c = 0; c < 4; ++c) acc[mt][nt][c] = 0.f;

    const float* Cb = C + (size_t)b * D * LC;
    const float* Qb = Q + (size_t)b * D * LQ;

    int qm = tid & 31, kr = tid >> 5;    // loader: m-quad, k-row

    uint4 pa[4], pb[4];
#pragma unroll
    for (int p = 0; p < 4; ++p) {        // prefetch chunk 0
        int k = kr + 8 * p;
        float w3 = w[2 * D + k];
        float4 v = *(const float4*)(Cb + (size_t)k * LC + i0 + 4 * qm);
        v.x *= w3; v.y *= w3; v.z *= w3; v.w *= w3;
        pa[p] = f2t4(v);
        pb[p] = f2t4(*(const float4*)(Qb + (size_t)k * LQ + j0 + 4 * qm));
    }

    for (int kc = 0; kc < D; kc += 32) {
        __syncthreads();
#pragma unroll
        for (int p = 0; p < 4; ++p) {
            *(uint4*)&As[kr + 8 * p][4 * qm] = pa[p];
            *(uint4*)&Bs[kr + 8 * p][4 * qm] = pb[p];
        }
        __syncthreads();
        if (kc + 32 < D) {
#pragma unroll
            for (int p = 0; p < 4; ++p) {
                int k = kc + 32 + kr + 8 * p;
                float w3 = w[2 * D + k];
                float4 v = *(const float4*)(Cb + (size_t)k * LC + i0 + 4 * qm);
                v.x *= w3; v.y *= w3; v.z *= w3; v.w *= w3;
                pa[p] = f2t4(v);
                pb[p] = f2t4(*(const float4*)(Qb + (size_t)k * LQ + j0 + 4 * qm));
            }
        }
#pragma unroll
        for (int k8 = 0; k8 < 4; ++k8) {
            int kk = 8 * k8;
            unsigned a[2][4];
#pragma unroll
            for (int mt = 0; mt < 2; ++mt) {
                int R = wm * 32 + mt * 16 + g;
                a[mt][0] = As[kk + t][R];
                a[mt][1] = As[kk + t][R + 8];
                a[mt][2] = As[kk + t + 4][R];
                a[mt][3] = As[kk + t + 4][R + 8];
            }
#pragma unroll
            for (int nt = 0; nt < 8; ++nt) {
                int NN = wn * 64 + nt * 8 + g;
                unsigned bb[2] = { Bs[kk + t][NN], Bs[kk + t + 4][NN] };
#pragma unroll
                for (int mt = 0; mt < 2; ++mt) mma8(acc[mt][nt], a[mt], bb);
            }
        }
    }

    // ---- epilogue: exp into acc, row/col partial sums ----
    __syncthreads();
    if (tid < 128) {
        scw[tid]  = g_cw1[b * LC + i0 + tid];
        sfcs[tid] = g_fc[b * LC + i0 + tid];
        srow[tid] = 0.f;
    } else {
        int j = tid - 128;
        sqw[j]  = g_qw2[b * LQ + j0 + j];
        sfqs[j] = g_fq[b * LQ + j0 + j];
        scol[j] = 0.f;
    }
    __syncthreads();

    float rowp[4] = {0.f, 0.f, 0.f, 0.f};
    float colp[16];
#pragma unroll
    for (int c = 0; c < 16; ++c) colp[c] = 0.f;

#pragma unroll
    for (int mt = 0; mt < 2; ++mt)
#pragma unroll
        for (int half = 0; half < 2; ++half) {
            int rl = wm * 32 + mt * 16 + g + 8 * half;
            float cwv = scw[rl], fcv = sfcs[rl];
#pragma unroll
            for (int nt = 0; nt < 8; ++nt) {
                int cl = wn * 64 + nt * 8 + 2 * t;
                float e0 = __expf(acc[mt][nt][half * 2 + 0] + cwv + sqw[cl]);
                float e1 = __expf(acc[mt][nt][half * 2 + 1] + cwv + sqw[cl + 1]);
                acc[mt][nt][half * 2 + 0] = e0;
                acc[mt][nt][half * 2 + 1] = e1;
                rowp[mt * 2 + half] += e0 * sfqs[cl] + e1 * sfqs[cl + 1];
                colp[nt * 2 + 0] += e0 * fcv;
                colp[nt * 2 + 1] += e1 * fcv;
            }
        }

#pragma unroll
    for (int r = 0; r < 4; ++r) {
        rowp[r] += __shfl_xor_sync(0xffffffffu, rowp[r], 1);
        rowp[r] += __shfl_xor_sync(0xffffffffu, rowp[r], 2);
    }
    if (t == 0) {
#pragma unroll
        for (int mt = 0; mt < 2; ++mt)
#pragma unroll
            for (int half = 0; half < 2; ++half)
                atomicAdd(&srow[wm * 32 + mt * 16 + g + 8 * half], rowp[mt * 2 + half]);
    }
#pragma unroll
    for (int c = 0; c < 16; ++c) {
        colp[c] += __shfl_xor_sync(0xffffffffu, colp[c], 4);
        colp[c] += __shfl_xor_sync(0xffffffffu, colp[c], 8);
        colp[c] += __shfl_xor_sync(0xffffffffu, colp[c], 16);
    }
    if (g == 0) {
#pragma unroll
        for (int nt = 0; nt < 8; ++nt)
#pragma unroll
            for (int par = 0; par < 2; ++par)
                atomicAdd(&scol[wn * 64 + nt * 8 + 2 * t + par], colp[nt * 2 + par]);
    }
    __syncthreads();
    if (tid < 128) atomicAdd(&g_rowsum[b * LC + i0 + tid], srow[tid]);
    else           atomicAdd(&g_colsum[b * LQ + j0 + tid - 128], scol[tid - 128]);

    // ---- coalesced E store via smem transpose (2 chunks of 64 rows) ----
    int r2 = tid >> 4, c16 = tid & 15;
#pragma unroll
    for (int ch = 0; ch < 2; ++ch) {
        __syncthreads();
        if ((wm >> 1) == ch) {
#pragma unroll
            for (int mt = 0; mt < 2; ++mt)
#pragma unroll
                for (int half = 0; half < 2; ++half) {
                    int rowl = (wm & 1) * 32 + mt * 16 + g + 8 * half;
#pragma unroll
                    for (int nt = 0; nt < 8; ++nt) {
                        int col = wn * 64 + nt * 8 + 2 * t;
                        tr[rowl * SA + col]     = acc[mt][nt][half * 2 + 0];
                        tr[rowl * SA + col + 1] = acc[mt][nt][half * 2 + 1];
                    }
                }
        }
        __syncthreads();
        float* dst = g_E + ((size_t)b * LC + i0 + ch * 64) * LQ + j0;
#pragma unroll
        for (int rr = 0; rr < 4; ++rr)
#pragma unroll
            for (int seg = 0; seg < 2; ++seg) {
                int row = r2 + 16 * rr;
                *(float4*)(dst + (size_t)row * LQ + seg * 64 + 4 * c16) =
                    *(float4*)&tr[row * SA + seg * 64 + 4 * c16];
            }
    }
}

// ---------------- K4: M[j][dd] = (sum_i E[i][j]*fc[i]*C[dd][i]) / colsum[j] --
// grid (LQ/128, B), 256 thr.  M=j(128) N=dd(128) K=i(1024)
__global__ __launch_bounds__(256, 2) void k4_m(const float* __restrict__ C) {
    int b = blockIdx.y, j0 = blockIdx.x * 128;

    __shared__ __align__(16) unsigned SMB[2 * 32 * SA];
    unsigned (*As)[SA] = (unsigned(*)[SA])SMB;
    unsigned (*Bs)[SA] = (unsigned(*)[SA])(SMB + 32 * SA);
    float* tr = (float*)SMB;

    int tid = threadIdx.x;
    int wid = tid >> 5, lane = tid & 31, g = lane >> 2, t = lane & 3;
    int wm = wid & 3, wn = wid >> 2;

    float acc[2][8][4];
#pragma unroll
    for (int mt = 0; mt < 2; ++mt)
#pragma unroll
        for (int nt = 0; nt < 8; ++nt)
#pragma unroll
            for (int c = 0; c < 4; ++c) acc[mt][nt][c] = 0.f;

    const float* Cb = C + (size_t)b * D * LC;
    const float* Eb = g_E + (size_t)b * LC * LQ;

    int qm = tid & 31, kr = tid >> 5;     // A loader
    int dd = tid & 127, kq = tid >> 7;    // B loader (transpose)

    uint4 va[4], vb[4];
#pragma unroll
    for (int p = 0; p < 4; ++p) {
        int i = kr + 8 * p;
        float f = g_fc[b * LC + i];
        float4 v = *(const float4*)(Eb + (size_t)i * LQ + j0 + 4 * qm);
        v.x *= f; v.y *= f; v.z *= f; v.w *= f;
        va[p] = f2t4(v);
        vb[p] = f2t4(*(const float4*)(Cb + (size_t)dd * LC + 4 * (kq + 2 * p)));
    }

    for (int kc = 0; kc < LC; kc += 32) {
        __syncthreads();
#pragma unroll
        for (int p = 0; p < 4; ++p) {
            *(uint4*)&As[kr + 8 * p][4 * qm] = va[p];
            int kb = 4 * (kq + 2 * p);
            Bs[kb + 0][dd] = vb[p].x;
            Bs[kb + 1][dd] = vb[p].y;
            Bs[kb + 2][dd] = vb[p].z;
            Bs[kb + 3][dd] = vb[p].w;
        }
        __syncthreads();
        if (kc + 32 < LC) {
#pragma unroll
            for (int p = 0; p < 4; ++p) {
                int i = kc + 32 + kr + 8 * p;
                float f = g_fc[b * LC + i];
                float4 v = *(const float4*)(Eb + (size_t)i * LQ + j0 + 4 * qm);
                v.x *= f; v.y *= f; v.z *= f; v.w *= f;
                va[p] = f2t4(v);
                vb[p] = f2t4(*(const float4*)(Cb + (size_t)dd * LC + kc + 32 + 4 * (kq + 2 * p)));
            }
        }
#pragma unroll
        for (int k8 = 0; k8 < 4; ++k8) {
            int kk = 8 * k8;
            unsigned a[2][4];
#pragma unroll
            for (int mt = 0; mt < 2; ++mt) {
                int R = wm * 32 + mt * 16 + g;
                a[mt][0] = As[kk + t][R];
                a[mt][1] = As[kk + t][R + 8];
                a[mt][2] = As[kk + t + 4][R];
                a[mt][3] = As[kk + t + 4][R + 8];
            }
#pragma unroll
            for (int nt = 0; nt < 8; ++nt) {
                int NN = wn * 64 + nt * 8 + g;
                unsigned bb[2] = { Bs[kk + t][NN], Bs[kk + t + 4][NN] };
#pragma unroll
                for (int mt = 0; mt < 2; ++mt) mma8(acc[mt][nt], a[mt], bb);
            }
        }
    }

    // ---- coalesced M store via smem transpose (2 chunks of 64 j-rows) ----
    int r2 = tid >> 4, c16 = tid & 15;
#pragma unroll
    for (int ch = 0; ch < 2; ++ch) {
        __syncthreads();
        if ((wm >> 1) == ch) {
#pragma unroll
            for (int mt = 0; mt < 2; ++mt)
#pragma unroll
                for (int half = 0; half < 2; ++half) {
                    int rowl = (wm & 1) * 32 + mt * 16 + g + 8 * half;
                    float ci = 1.0f / g_colsum[b * LQ + j0 + ch * 64 + rowl];
#pragma unroll
                    for (int nt = 0; nt < 8; ++nt) {
                        int col = wn * 64 + nt * 8 + 2 * t;
                        tr[rowl * SA + col]     = acc[mt][nt][half * 2 + 0] * ci;
                        tr[rowl * SA + col + 1] = acc[mt][nt][half * 2 + 1] * ci;
                    }
                }
        }
        __syncthreads();
        float* dst = g_M + ((size_t)b * LQ + j0 + ch * 64) * D;
#pragma unroll
        for (int rr = 0; rr < 4; ++rr)
#pragma unroll
            for (int seg = 0; seg < 2; ++seg) {
                int row = r2 + 16 * rr;
                *(float4*)(dst + (size_t)row * D + seg * 64 + 4 * c16) =
                    *(float4*)&tr[row * SA + seg * 64 + 4 * c16];
            }
    }
}

// ---------------- K5: A & Bmat (dual GEMM) + 4 output channels ----------------
// grid (D/64, LC/128, B), 256 thr.  M=i(128) N=dd(64) K=j(256)
__global__ __launch_bounds__(256, 2) void k5_out(const float* __restrict__ C,
                                                 const float* __restrict__ Q,
                                                 float* __restrict__ out) {
    int b = blockIdx.z, i0 = blockIdx.y * 128, dd0 = blockIdx.x * 64;

    __shared__ __align__(16) unsigned SMB[32 * SA + 2 * 32 * SB];  // As|Bq|Bm; tr[64][SA]
    unsigned (*As)[SA] = (unsigned(*)[SA])SMB;
    unsigned (*Bq)[SB] = (unsigned(*)[SB])(SMB + 32 * SA);
    unsigned (*Bm)[SB] = (unsigned(*)[SB])(SMB + 32 * SA + 32 * SB);
    float* tr = (float*)SMB;
    __shared__ float sfq[LQ];

    int tid = threadIdx.x;
    int wid = tid >> 5, lane = tid & 31, g = lane >> 2, t = lane & 3;
    int wm = wid & 3, wn = wid >> 2;     // warp tile: 32(m) x 32(n)

    sfq[tid] = g_fq[b * LQ + tid];

    float accA[2][4][4], accB[2][4][4];
#pragma unroll
    for (int mt = 0; mt < 2; ++mt)
#pragma unroll
        for (int nt = 0; nt < 4; ++nt)
#pragma unroll
            for (int c = 0; c < 4; ++c) { accA[mt][nt][c] = 0.f; accB[mt][nt][c] = 0.f; }

    const float* Cb = C + (size_t)b * D * LC;
    const float* Qb = Q + (size_t)b * D * LQ;
    const float* Eb = g_E + (size_t)b * LC * LQ;
    const float* Mb = g_M + (size_t)b * LQ * D;

    int ia = tid & 127, kqa = tid >> 7;        // A loader (transpose)
    int dq = tid & 63,  kq2 = (tid >> 6) & 3;  // Bq loader (transpose)
    int qn = tid & 15,  krm = tid >> 4;        // Bm loader (direct)

    float4 ea[4];
    uint4 qa[2], ma[2];
#pragma unroll
    for (int p = 0; p < 4; ++p)
        ea[p] = *(const float4*)(Eb + (size_t)(i0 + ia) * LQ + 4 * (kqa + 2 * p));
#pragma unroll
    for (int p = 0; p < 2; ++p) {
        qa[p] = f2t4(*(const float4*)(Qb + (size_t)(dd0 + dq) * LQ + 4 * (kq2 + 4 * p)));
        ma[p] = f2t4(*(const float4*)(Mb + (size_t)(krm + 16 * p) * D + dd0 + 4 * qn));
    }

    for (int kc = 0; kc < LQ; kc += 32) {
        __syncthreads();
#pragma unroll
        for (int p = 0; p < 4; ++p) {
            int ka = 4 * (kqa + 2 * p);
            As[ka + 0][ia] = f2t(ea[p].x * sfq[kc + ka + 0]);
            As[ka + 1][ia] = f2t(ea[p].y * sfq[kc + ka + 1]);
            As[ka + 2][ia] = f2t(ea[p].z * sfq[kc + ka + 2]);
            As[ka + 3][ia] = f2t(ea[p].w * sfq[kc + ka + 3]);
        }
#pragma unroll
        for (int p = 0; p < 2; ++p) {
            int kb = 4 * (kq2 + 4 * p);
            Bq[kb + 0][dq] = qa[p].x;
            Bq[kb + 1][dq] = qa[p].y;
            Bq[kb + 2][dq] = qa[p].z;
            Bq[kb + 3][dq] = qa[p].w;
            *(uint4*)&Bm[krm + 16 * p][4 * qn] = ma[p];
        }
        __syncthreads();
        if (kc + 32 < LQ) {
#pragma unroll
            for (int p = 0; p < 4; ++p)
                ea[p] = *(const float4*)(Eb + (size_t)(i0 + ia) * LQ + kc + 32 + 4 * (kqa + 2 * p));
#pragma unroll
            for (int p = 0; p < 2; ++p) {
                qa[p] = f2t4(*(const float4*)(Qb + (size_t)(dd0 + dq) * LQ + kc + 32 + 4 * (kq2 + 4 * p)));
                ma[p] = f2t4(*(const float4*)(Mb + (size_t)(kc + 32 + krm + 16 * p) * D + dd0 + 4 * qn));
            }
        }
#pragma unroll
        for (int k8 = 0; k8 < 4; ++k8) {
            int kk = 8 * k8;
            unsigned a[2][4];
#pragma unroll
            for (int mt = 0; mt < 2; ++mt) {
                int R = wm * 32 + mt * 16 + g;
                a[mt][0] = As[kk + t][R];
                a[mt][1] = As[kk + t][R + 8];
                a[mt][2] = As[kk + t + 4][R];
                a[mt][3] = As[kk + t + 4][R + 8];
            }
#pragma unroll
            for (int nt = 0; nt < 4; ++nt) {
                int NN = wn * 32 + nt * 8 + g;
                unsigned bq[2] = { Bq[kk + t][NN], Bq[kk + t + 4][NN] };
                unsigned bm[2] = { Bm[kk + t][NN], Bm[kk + t + 4][NN] };
#pragma unroll
                for (int mt = 0; mt < 2; ++mt) {
                    mma8(accA[mt][nt], a[mt], bq);
                    mma8(accB[mt][nt], a[mt], bm);
                }
            }
        }
    }

    // ---- epilogue: rowsum scale, transpose in smem, coalesced stores ----
    float rinv[2][2];
#pragma unroll
    for (int mt = 0; mt < 2; ++mt)
#pragma unroll
        for (int half = 0; half < 2; ++half)
            rinv[mt][half] = 1.0f / g_rowsum[b * LC + i0 + wm * 32 + mt * 16 + g + 8 * half];

    int r2 = tid >> 4, c16 = tid & 15;
    size_t ob = (size_t)b * 4 * D * LC;
    const float* Csrc = Cb + (size_t)dd0 * LC + i0;
    float* o0 = out + ob + (size_t)dd0 * LC + i0;

    // phase A: channels 0 (Ct), 1 (A), 2 (Ct*A)
    __syncthreads();
#pragma unroll
    for (int mt = 0; mt < 2; ++mt)
#pragma unroll
        for (int half = 0; half < 2; ++half) {
            int iil = wm * 32 + mt * 16 + g + 8 * half;
#pragma unroll
            for (int nt = 0; nt < 4; ++nt) {
                int ddl = wn * 32 + nt * 8 + 2 * t;
                tr[ddl * SA + iil]       = accA[mt][nt][half * 2 + 0] * rinv[mt][half];
                tr[(ddl + 1) * SA + iil] = accA[mt][nt][half * 2 + 1] * rinv[mt][half];
            }
        }
    __syncthreads();
#pragma unroll
    for (int rr = 0; rr < 4; ++rr)
#pragma unroll
        for (int seg = 0; seg < 2; ++seg) {
            int row = r2 + 16 * rr;
            int off = seg * 64 + 4 * c16;
            float4 a4 = *(float4*)&tr[row * SA + off];
            float4 c4 = *(const float4*)(Csrc + (size_t)row * LC + off);
            size_t go = (size_t)row * LC + off;
            *(float4*)(o0 + go) = c4;
            *(float4*)(o0 + (size_t)D * LC + go) = a4;
            *(float4*)(o0 + (size_t)2 * D * LC + go) =
                make_float4(c4.x * a4.x, c4.y * a4.y, c4.z * a4.z, c4.w * a4.w);
        }

    // phase B: channel 3 (Ct*Bmat)
    __syncthreads();
#pragma unroll
    for (int mt = 0; mt < 2; ++mt)
#pragma unroll
        for (int half = 0; half < 2; ++half) {
            int iil = wm * 32 + mt * 16 + g + 8 * half;
#pragma unroll
            for (int nt = 0; nt < 4; ++nt) {
                int ddl = wn * 32 + nt * 8 + 2 * t;
                tr[ddl * SA + iil]       = accB[mt][nt][half * 2 + 0] * rinv[mt][half];
                tr[(ddl + 1) * SA + iil] = accB[mt][nt][half * 2 + 1] * rinv[mt][half];
            }
        }
    __syncthreads();
#pragma unroll
    for (int rr = 0; rr < 4; ++rr)
#pragma unroll
        for (int seg = 0; seg < 2; ++seg) {
            int row = r2 + 16 * rr;
            int off = seg * 64 + 4 * c16;
            float4 b4 = *(float4*)&tr[row * SA + off];
            float4 c4 = *(const float4*)(Csrc + (size_t)row * LC + off);
            *(float4*)(o0 + (size_t)3 * D * LC + (size_t)row * LC + off) =
                make_float4(c4.x * b4.x, c4.y * b4.y, c4.z * b4.z, c4.w * b4.w);
        }
}

// ---------------- launch ------------------------------------------------------
extern "C" void kernel_launch(void* const* d_in, const int* in_sizes, int n_in,
                              void* d_out, int out_size) {
    const float* C = (const float*)d_in[0];
    const float* Q = (const float*)d_in[1];
    const float* cmask = (const float*)d_in[2];
    const float* qmask = (const float*)d_in[3];
    const float* w = (const float*)d_in[4];
    float* out = (float*)d_out;

    k0_setup<<<(B * LC + B * LQ) / 256, 256>>>(C, Q, cmask, qmask, w);

    dim3 g1(LQ / 128, LC / 128, B);
    k1_score<<<g1, 256>>>(C, Q, w);

    dim3 g4(LQ / 128, B);
    k4_m<<<g4, 256>>>(C);

    dim3 g5(D / 64, LC / 128, B);
    k5_out<<<g5, 256>>>(C, Q, out);
}

// round 14
// speedup vs baseline: 1.1138x; 1.1050x over previous
#include <cuda_runtime.h>
#include <math.h>

#define B    64
#define D    128
#define LC   1024
#define LQ   256
#define NEG_INF -1e30f
#define SA   136     // smem row stride (136%32==8 -> conflict-free fragment reads)
#define SB   72      // smem row stride for 64-wide tiles (72%32==8)

// ---------------- scratch (device globals: no allocation allowed) ----------------
__device__ float g_E[(size_t)B * LC * LQ];    // exp(S)  [b][i][j], 64 MiB
__device__ float g_Et[(size_t)B * LQ * LC];   // exp(S)T [b][j][i], 64 MiB
__device__ float g_Ct[(size_t)B * LC * D];    // C^T [b][i][dd], 32 MiB
__device__ float g_Qt[(size_t)B * LQ * D];    // Q^T [b][j][dd], 8 MiB
__device__ float g_M[(size_t)B * LQ * D];     // S2^T @ Ct (already / colsum)
__device__ float g_rowsum[B * LC];
__device__ float g_colsum[B * LQ];
__device__ float g_cw1[B * LC];
__device__ float g_qw2[B * LQ];
__device__ float g_fc[B * LC];
__device__ float g_fq[B * LQ];

// ---------------- tf32 helpers ----------------
__device__ __forceinline__ unsigned f2t(float x) {
    unsigned u; asm("cvt.rna.tf32.f32 %0, %1;" : "=r"(u) : "f"(x)); return u;
}
__device__ __forceinline__ uint4 f2t4(float4 v) {
    return make_uint4(f2t(v.x), f2t(v.y), f2t(v.z), f2t(v.w));
}
__device__ __forceinline__ void mma8(float* c, const unsigned* a, const unsigned* b) {
    asm volatile(
        "mma.sync.aligned.m16n8k8.row.col.f32.tf32.tf32.f32 "
        "{%0,%1,%2,%3},{%4,%5,%6,%7},{%8,%9},{%0,%1,%2,%3};"
        : "+f"(c[0]), "+f"(c[1]), "+f"(c[2]), "+f"(c[3])
        : "r"(a[0]), "r"(a[1]), "r"(a[2]), "r"(a[3]), "r"(b[0]), "r"(b[1]));
}

// ---------------- transpose body: [rows][cols] -> [cols][rows], one batch ----
// Device-side only; global array operands are bound in the wrapper kernels so
// no __device__ symbol is ever passed from host code.
template<int ROWS, int COLS>
__device__ __forceinline__ void trb(const float* __restrict__ s, float* __restrict__ d) {
    __shared__ float tile[32][33];
    int c0 = blockIdx.x * 32;
    int r0 = blockIdx.y * 32;
    int tx = threadIdx.x, ty = threadIdx.y;
#pragma unroll
    for (int k = 0; k < 32; k += 8)
        tile[ty + k][tx] = s[(size_t)(r0 + ty + k) * COLS + c0 + tx];
    __syncthreads();
#pragma unroll
    for (int k = 0; k < 32; k += 8)
        d[(size_t)(c0 + ty + k) * ROWS + r0 + tx] = tile[tx][ty + k];
}

__global__ void kTR_Ct(const float* __restrict__ C) {
    int b = blockIdx.z;
    trb<D, LC>(C + (size_t)b * D * LC, g_Ct + (size_t)b * LC * D);
}
__global__ void kTR_Qt(const float* __restrict__ Q) {
    int b = blockIdx.z;
    trb<D, LQ>(Q + (size_t)b * D * LQ, g_Qt + (size_t)b * LQ * D);
}
__global__ void kTR_Et() {
    int b = blockIdx.z;
    trb<LC, LQ>(g_E + (size_t)b * LC * LQ, g_Et + (size_t)b * LQ * LC);
}

// ---------------- K0: biases, mask factors, zero accumulators ----------------
__global__ void k0_setup(const float* __restrict__ C, const float* __restrict__ Q,
                         const float* __restrict__ cmask, const float* __restrict__ qmask,
                         const float* __restrict__ w) {
    int idx = blockIdx.x * 256 + threadIdx.x;
    if (idx < B * LC) {
        int b = idx >> 10;
        int i = idx & (LC - 1);
        const float* cp = C + (size_t)b * D * LC + i;
        float s = 0.f;
#pragma unroll 4
        for (int dd = 0; dd < D; ++dd) s = fmaf(cp[(size_t)dd * LC], w[dd], s);
        g_cw1[idx] = s;
        g_fc[idx] = __expf((1.0f - cmask[idx]) * NEG_INF);
        g_rowsum[idx] = 0.f;
    } else {
        int t = idx - B * LC;
        if (t < B * LQ) {
            int b = t >> 8;
            int j = t & (LQ - 1);
            const float* qp = Q + (size_t)b * D * LQ + j;
            float s = 0.f;
#pragma unroll 4
            for (int dd = 0; dd < D; ++dd) s = fmaf(qp[(size_t)dd * LQ], w[D + dd], s);
            g_qw2[t] = s;
            g_fq[t] = __expf((1.0f - qmask[t]) * NEG_INF);
            g_colsum[t] = 0.f;
        }
    }
}

// ---------------- K1: E = exp(S) + row/col exp-sums (tf32 MMA) ---------------
// EXACT round-11 version (E store only).
__global__ __launch_bounds__(256, 2) void k1_score(const float* __restrict__ C,
                                                   const float* __restrict__ Q,
                                                   const float* __restrict__ w) {
    int b = blockIdx.z, i0 = blockIdx.y * 128, j0 = blockIdx.x * 128;

    __shared__ __align__(16) unsigned SMB[2 * 32 * SA];   // As|Bs; reused as tr[64][SA]
    unsigned (*As)[SA] = (unsigned(*)[SA])SMB;
    unsigned (*Bs)[SA] = (unsigned(*)[SA])(SMB + 32 * SA);
    float* tr = (float*)SMB;
    __shared__ float scw[128], sfcs[128], sqw[128], sfqs[128], srow[128], scol[128];

    int tid = threadIdx.x;
    int wid = tid >> 5, lane = tid & 31, g = lane >> 2, t = lane & 3;
    int wm = wid & 3, wn = wid >> 2;     // warp tile: 32(m) x 64(n)

    float acc[2][8][4];
#pragma unroll
    for (int mt = 0; mt < 2; ++mt)
#pragma unroll
        for (int nt = 0; nt < 8; ++nt)
#pragma unroll
            for (int c = 0; c < 4; ++c) acc[mt][nt][c] = 0.f;

    const float* Cb = C + (size_t)b * D * LC;
    const float* Qb = Q + (size_t)b * D * LQ;

    int qm = tid & 31, kr = tid >> 5;    // loader: m-quad, k-row

    uint4 pa[4], pb[4];
#pragma unroll
    for (int p = 0; p < 4; ++p) {        // prefetch chunk 0
        int k = kr + 8 * p;
        float w3 = w[2 * D + k];
        float4 v = *(const float4*)(Cb + (size_t)k * LC + i0 + 4 * qm);
        v.x *= w3; v.y *= w3; v.z *= w3; v.w *= w3;
        pa[p] = f2t4(v);
        pb[p] = f2t4(*(const float4*)(Qb + (size_t)k * LQ + j0 + 4 * qm));
    }

    for (int kc = 0; kc < D; kc += 32) {
        __syncthreads();
#pragma unroll
        for (int p = 0; p < 4; ++p) {
            *(uint4*)&As[kr + 8 * p][4 * qm] = pa[p];
            *(uint4*)&Bs[kr + 8 * p][4 * qm] = pb[p];
        }
        __syncthreads();
        if (kc + 32 < D) {
#pragma unroll
            for (int p = 0; p < 4; ++p) {
                int k = kc + 32 + kr + 8 * p;
                float w3 = w[2 * D + k];
                float4 v = *(const float4*)(Cb + (size_t)k * LC + i0 + 4 * qm);
                v.x *= w3; v.y *= w3; v.z *= w3; v.w *= w3;
                pa[p] = f2t4(v);
                pb[p] = f2t4(*(const float4*)(Qb + (size_t)k * LQ + j0 + 4 * qm));
            }
        }
#pragma unroll
        for (int k8 = 0; k8 < 4; ++k8) {
            int kk = 8 * k8;
            unsigned a[2][4];
#pragma unroll
            for (int mt = 0; mt < 2; ++mt) {
                int R = wm * 32 + mt * 16 + g;
                a[mt][0] = As[kk + t][R];
                a[mt][1] = As[kk + t][R + 8];
                a[mt][2] = As[kk + t + 4][R];
                a[mt][3] = As[kk + t + 4][R + 8];
            }
#pragma unroll
            for (int nt = 0; nt < 8; ++nt) {
                int NN = wn * 64 + nt * 8 + g;
                unsigned bb[2] = { Bs[kk + t][NN], Bs[kk + t + 4][NN] };
#pragma unroll
                for (int mt = 0; mt < 2; ++mt) mma8(acc[mt][nt], a[mt], bb);
            }
        }
    }

    // ---- epilogue: exp into acc, row/col partial sums ----
    __syncthreads();
    if (tid < 128) {
        scw[tid]  = g_cw1[b * LC + i0 + tid];
        sfcs[tid] = g_fc[b * LC + i0 + tid];
        srow[tid] = 0.f;
    } else {
        int j = tid - 128;
        sqw[j]  = g_qw2[b * LQ + j0 + j];
        sfqs[j] = g_fq[b * LQ + j0 + j];
        scol[j] = 0.f;
    }
    __syncthreads();

    float rowp[4] = {0.f, 0.f, 0.f, 0.f};
    float colp[16];
#pragma unroll
    for (int c = 0; c < 16; ++c) colp[c] = 0.f;

#pragma unroll
    for (int mt = 0; mt < 2; ++mt)
#pragma unroll
        for (int half = 0; half < 2; ++half) {
            int rl = wm * 32 + mt * 16 + g + 8 * half;
            float cwv = scw[rl], fcv = sfcs[rl];
#pragma unroll
            for (int nt = 0; nt < 8; ++nt) {
                int cl = wn * 64 + nt * 8 + 2 * t;
                float e0 = __expf(acc[mt][nt][half * 2 + 0] + cwv + sqw[cl]);
                float e1 = __expf(acc[mt][nt][half * 2 + 1] + cwv + sqw[cl + 1]);
                acc[mt][nt][half * 2 + 0] = e0;
                acc[mt][nt][half * 2 + 1] = e1;
                rowp[mt * 2 + half] += e0 * sfqs[cl] + e1 * sfqs[cl + 1];
                colp[nt * 2 + 0] += e0 * fcv;
                colp[nt * 2 + 1] += e1 * fcv;
            }
        }

#pragma unroll
    for (int r = 0; r < 4; ++r) {
        rowp[r] += __shfl_xor_sync(0xffffffffu, rowp[r], 1);
        rowp[r] += __shfl_xor_sync(0xffffffffu, rowp[r], 2);
    }
    if (t == 0) {
#pragma unroll
        for (int mt = 0; mt < 2; ++mt)
#pragma unroll
            for (int half = 0; half < 2; ++half)
                atomicAdd(&srow[wm * 32 + mt * 16 + g + 8 * half], rowp[mt * 2 + half]);
    }
#pragma unroll
    for (int c = 0; c < 16; ++c) {
        colp[c] += __shfl_xor_sync(0xffffffffu, colp[c], 4);
        colp[c] += __shfl_xor_sync(0xffffffffu, colp[c], 8);
        colp[c] += __shfl_xor_sync(0xffffffffu, colp[c], 16);
    }
    if (g == 0) {
#pragma unroll
        for (int nt = 0; nt < 8; ++nt)
#pragma unroll
            for (int par = 0; par < 2; ++par)
                atomicAdd(&scol[wn * 64 + nt * 8 + 2 * t + par], colp[nt * 2 + par]);
    }
    __syncthreads();
    if (tid < 128) atomicAdd(&g_rowsum[b * LC + i0 + tid], srow[tid]);
    else           atomicAdd(&g_colsum[b * LQ + j0 + tid - 128], scol[tid - 128]);

    // ---- coalesced E store via smem transpose (2 chunks of 64 rows) ----
    int r2 = tid >> 4, c16 = tid & 15;
#pragma unroll
    for (int ch = 0; ch < 2; ++ch) {
        __syncthreads();
        if ((wm >> 1) == ch) {
#pragma unroll
            for (int mt = 0; mt < 2; ++mt)
#pragma unroll
                for (int half = 0; half < 2; ++half) {
                    int rowl = (wm & 1) * 32 + mt * 16 + g + 8 * half;
#pragma unroll
                    for (int nt = 0; nt < 8; ++nt) {
                        int col = wn * 64 + nt * 8 + 2 * t;
                        tr[rowl * SA + col]     = acc[mt][nt][half * 2 + 0];
                        tr[rowl * SA + col + 1] = acc[mt][nt][half * 2 + 1];
                    }
                }
        }
        __syncthreads();
        float* dst = g_E + ((size_t)b * LC + i0 + ch * 64) * LQ + j0;
#pragma unroll
        for (int rr = 0; rr < 4; ++rr)
#pragma unroll
            for (int seg = 0; seg < 2; ++seg) {
                int row = r2 + 16 * rr;
                *(float4*)(dst + (size_t)row * LQ + seg * 64 + 4 * c16) =
                    *(float4*)&tr[row * SA + seg * 64 + 4 * c16];
            }
    }
}

// ---------------- K4: M[j][dd] = (sum_i E[i][j]*fc[i]*Ct[i][dd]) / colsum[j] --
__global__ __launch_bounds__(256, 2) void k4_m() {
    int b = blockIdx.y, j0 = blockIdx.x * 128;

    __shared__ __align__(16) unsigned SMB[2 * 32 * SA];
    unsigned (*As)[SA] = (unsigned(*)[SA])SMB;
    unsigned (*Bs)[SA] = (unsigned(*)[SA])(SMB + 32 * SA);
    float* tr = (float*)SMB;

    int tid = threadIdx.x;
    int wid = tid >> 5, lane = tid & 31, g = lane >> 2, t = lane & 3;
    int wm = wid & 3, wn = wid >> 2;

    float acc[2][8][4];
#pragma unroll
    for (int mt = 0; mt < 2; ++mt)
#pragma unroll
        for (int nt = 0; nt < 8; ++nt)
#pragma unroll
            for (int c = 0; c < 4; ++c) acc[mt][nt][c] = 0.f;

    const float* Eb = g_E + (size_t)b * LC * LQ;
    const float* Ctb = g_Ct + (size_t)b * LC * D;

    int qm = tid & 31, kr = tid >> 5;

    uint4 va[4], vb[4];
#pragma unroll
    for (int p = 0; p < 4; ++p) {
        int i = kr + 8 * p;
        float f = g_fc[b * LC + i];
        float4 v = *(const float4*)(Eb + (size_t)i * LQ + j0 + 4 * qm);
        v.x *= f; v.y *= f; v.z *= f; v.w *= f;
        va[p] = f2t4(v);
        vb[p] = f2t4(*(const float4*)(Ctb + (size_t)i * D + 4 * qm));
    }

    for (int kc = 0; kc < LC; kc += 32) {
        __syncthreads();
#pragma unroll
        for (int p = 0; p < 4; ++p) {
            *(uint4*)&As[kr + 8 * p][4 * qm] = va[p];
            *(uint4*)&Bs[kr + 8 * p][4 * qm] = vb[p];
        }
        __syncthreads();
        if (kc + 32 < LC) {
#pragma unroll
            for (int p = 0; p < 4; ++p) {
                int i = kc + 32 + kr + 8 * p;
                float f = g_fc[b * LC + i];
                float4 v = *(const float4*)(Eb + (size_t)i * LQ + j0 + 4 * qm);
                v.x *= f; v.y *= f; v.z *= f; v.w *= f;
                va[p] = f2t4(v);
                vb[p] = f2t4(*(const float4*)(Ctb + (size_t)i * D + 4 * qm));
            }
        }
#pragma unroll
        for (int k8 = 0; k8 < 4; ++k8) {
            int kk = 8 * k8;
            unsigned a[2][4];
#pragma unroll
            for (int mt = 0; mt < 2; ++mt) {
                int R = wm * 32 + mt * 16 + g;
                a[mt][0] = As[kk + t][R];
                a[mt][1] = As[kk + t][R + 8];
                a[mt][2] = As[kk + t + 4][R];
                a[mt][3] = As[kk + t + 4][R + 8];
            }
#pragma unroll
            for (int nt = 0; nt < 8; ++nt) {
                int NN = wn * 64 + nt * 8 + g;
                unsigned bb[2] = { Bs[kk + t][NN], Bs[kk + t + 4][NN] };
#pragma unroll
                for (int mt = 0; mt < 2; ++mt) mma8(acc[mt][nt], a[mt], bb);
            }
        }
    }

    // ---- coalesced M store via smem transpose (2 chunks of 64 j-rows) ----
    int r2 = tid >> 4, c16 = tid & 15;
#pragma unroll
    for (int ch = 0; ch < 2; ++ch) {
        __syncthreads();
        if ((wm >> 1) == ch) {
#pragma unroll
            for (int mt = 0; mt < 2; ++mt)
#pragma unroll
                for (int half = 0; half < 2; ++half) {
                    int rowl = (wm & 1) * 32 + mt * 16 + g + 8 * half;
                    float ci = 1.0f / g_colsum[b * LQ + j0 + ch * 64 + rowl];
#pragma unroll
                    for (int nt = 0; nt < 8; ++nt) {
                        int col = wn * 64 + nt * 8 + 2 * t;
                        tr[rowl * SA + col]     = acc[mt][nt][half * 2 + 0] * ci;
                        tr[rowl * SA + col + 1] = acc[mt][nt][half * 2 + 1] * ci;
                    }
                }
        }
        __syncthreads();
        float* dst = g_M + ((size_t)b * LQ + j0 + ch * 64) * D;
#pragma unroll
        for (int rr = 0; rr < 4; ++rr)
#pragma unroll
            for (int seg = 0; seg < 2; ++seg) {
                int row = r2 + 16 * rr;
                *(float4*)(dst + (size_t)row * D + seg * 64 + 4 * c16) =
                    *(float4*)&tr[row * SA + seg * 64 + 4 * c16];
            }
    }
}

// ---------------- K5: A & Bmat (dual GEMM) + 4 output channels ----------------
__global__ __launch_bounds__(256, 2) void k5_out(const float* __restrict__ C,
                                                 float* __restrict__ out) {
    int b = blockIdx.z, i0 = blockIdx.y * 128, dd0 = blockIdx.x * 64;

    __shared__ __align__(16) unsigned SMB[32 * SA + 2 * 32 * SB];  // As|Bq|Bm; tr[64][SA]
    unsigned (*As)[SA] = (unsigned(*)[SA])SMB;
    unsigned (*Bq)[SB] = (unsigned(*)[SB])(SMB + 32 * SA);
    unsigned (*Bm)[SB] = (unsigned(*)[SB])(SMB + 32 * SA + 32 * SB);
    float* tr = (float*)SMB;
    __shared__ float sfq[LQ];

    int tid = threadIdx.x;
    int wid = tid >> 5, lane = tid & 31, g = lane >> 2, t = lane & 3;
    int wm = wid & 3, wn = wid >> 2;     // warp tile: 32(m) x 32(n)

    sfq[tid] = g_fq[b * LQ + tid];

    float accA[2][4][4], accB[2][4][4];
#pragma unroll
    for (int mt = 0; mt < 2; ++mt)
#pragma unroll
        for (int nt = 0; nt < 4; ++nt)
#pragma unroll
            for (int c = 0; c < 4; ++c) { accA[mt][nt][c] = 0.f; accB[mt][nt][c] = 0.f; }

    const float* Cb = C + (size_t)b * D * LC;
    const float* Etb = g_Et + (size_t)b * LQ * LC;
    const float* Qtb = g_Qt + (size_t)b * LQ * D;
    const float* Mb = g_M + (size_t)b * LQ * D;

    int qm = tid & 31, kr = tid >> 5;     // A loader (Et rows)
    int qn = tid & 15, krm = tid >> 4;    // Bq/Bm loaders

    float4 ea[4];
    uint4 qa[2], ma[2];
#pragma unroll
    for (int p = 0; p < 4; ++p)
        ea[p] = *(const float4*)(Etb + (size_t)(kr + 8 * p) * LC + i0 + 4 * qm);
#pragma unroll
    for (int p = 0; p < 2; ++p) {
        qa[p] = f2t4(*(const float4*)(Qtb + (size_t)(krm + 16 * p) * D + dd0 + 4 * qn));
        ma[p] = f2t4(*(const float4*)(Mb + (size_t)(krm + 16 * p) * D + dd0 + 4 * qn));
    }

    for (int kc = 0; kc < LQ; kc += 32) {
        __syncthreads();
#pragma unroll
        for (int p = 0; p < 4; ++p) {
            float s = sfq[kc + kr + 8 * p];
            *(uint4*)&As[kr + 8 * p][4 * qm] =
                f2t4(make_float4(ea[p].x * s, ea[p].y * s, ea[p].z * s, ea[p].w * s));
        }
#pragma unroll
        for (int p = 0; p < 2; ++p) {
            *(uint4*)&Bq[krm + 16 * p][4 * qn] = qa[p];
            *(uint4*)&Bm[krm + 16 * p][4 * qn] = ma[p];
        }
        __syncthreads();
        if (kc + 32 < LQ) {
#pragma unroll
            for (int p = 0; p < 4; ++p)
                ea[p] = *(const float4*)(Etb + (size_t)(kc + 32 + kr + 8 * p) * LC + i0 + 4 * qm);
#pragma unroll
            for (int p = 0; p < 2; ++p) {
                qa[p] = f2t4(*(const float4*)(Qtb + (size_t)(kc + 32 + krm + 16 * p) * D + dd0 + 4 * qn));
                ma[p] = f2t4(*(const float4*)(Mb + (size_t)(kc + 32 + krm + 16 * p) * D + dd0 + 4 * qn));
            }
        }
#pragma unroll
        for (int k8 = 0; k8 < 4; ++k8) {
            int kk = 8 * k8;
            unsigned a[2][4];
#pragma unroll
            for (int mt = 0; mt < 2; ++mt) {
                int R = wm * 32 + mt * 16 + g;
                a[mt][0] = As[kk + t][R];
                a[mt][1] = As[kk + t][R + 8];
                a[mt][2] = As[kk + t + 4][R];
                a[mt][3] = As[kk + t + 4][R + 8];
            }
#pragma unroll
            for (int nt = 0; nt < 4; ++nt) {
                int NN = wn * 32 + nt * 8 + g;
                unsigned bq[2] = { Bq[kk + t][NN], Bq[kk + t + 4][NN] };
                unsigned bm[2] = { Bm[kk + t][NN], Bm[kk + t + 4][NN] };
#pragma unroll
                for (int mt = 0; mt < 2; ++mt) {
                    mma8(accA[mt][nt], a[mt], bq);
                    mma8(accB[mt][nt], a[mt], bm);
                }
            }
        }
    }

    // ---- epilogue: rowsum scale, transpose in smem, coalesced stores ----
    float rinv[2][2];
#pragma unroll
    for (int mt = 0; mt < 2; ++mt)
#pragma unroll
        for (int half = 0; half < 2; ++half)
            rinv[mt][half] = 1.0f / g_rowsum[b * LC + i0 + wm * 32 + mt * 16 + g + 8 * half];

    int r2 = tid >> 4, c16 = tid & 15;
    size_t ob = (size_t)b * 4 * D * LC;
    const float* Csrc = Cb + (size_t)dd0 * LC + i0;
    float* o0 = out + ob + (size_t)dd0 * LC + i0;

    // phase A: channels 0 (Ct), 1 (A), 2 (Ct*A)
    __syncthreads();
#pragma unroll
    for (int mt = 0; mt < 2; ++mt)
#pragma unroll
        for (int half = 0; half < 2; ++half) {
            int iil = wm * 32 + mt * 16 + g + 8 * half;
#pragma unroll
            for (int nt = 0; nt < 4; ++nt) {
                int ddl = wn * 32 + nt * 8 + 2 * t;
                tr[ddl * SA + iil]       = accA[mt][nt][half * 2 + 0] * rinv[mt][half];
                tr[(ddl + 1) * SA + iil] = accA[mt][nt][half * 2 + 1] * rinv[mt][half];
            }
        }
    __syncthreads();
#pragma unroll
    for (int rr = 0; rr < 4; ++rr)
#pragma unroll
        for (int seg = 0; seg < 2; ++seg) {
            int row = r2 + 16 * rr;
            int off = seg * 64 + 4 * c16;
            float4 a4 = *(float4*)&tr[row * SA + off];
            float4 c4 = *(const float4*)(Csrc + (size_t)row * LC + off);
            size_t go = (size_t)row * LC + off;
            *(float4*)(o0 + go) = c4;
            *(float4*)(o0 + (size_t)D * LC + go) = a4;
            *(float4*)(o0 + (size_t)2 * D * LC + go) =
                make_float4(c4.x * a4.x, c4.y * a4.y, c4.z * a4.z, c4.w * a4.w);
        }

    // phase B: channel 3 (Ct*Bmat)
    __syncthreads();
#pragma unroll
    for (int mt = 0; mt < 2; ++mt)
#pragma unroll
        for (int half = 0; half < 2; ++half) {
            int iil = wm * 32 + mt * 16 + g + 8 * half;
#pragma unroll
            for (int nt = 0; nt < 4; ++nt) {
                int ddl = wn * 32 + nt * 8 + 2 * t;
                tr[ddl * SA + iil]       = accB[mt][nt][half * 2 + 0] * rinv[mt][half];
                tr[(ddl + 1) * SA + iil] = accB[mt][nt][half * 2 + 1] * rinv[mt][half];
            }
        }
    __syncthreads();
#pragma unroll
    for (int rr = 0; rr < 4; ++rr)
#pragma unroll
        for (int seg = 0; seg < 2; ++seg) {
            int row = r2 + 16 * rr;
            int off = seg * 64 + 4 * c16;
            float4 b4 = *(float4*)&tr[row * SA + off];
            float4 c4 = *(const float4*)(Csrc + (size_t)row * LC + off);
            *(float4*)(o0 + (size_t)3 * D * LC + (size_t)row * LC + off) =
                make_float4(c4.x * b4.x, c4.y * b4.y, c4.z * b4.z, c4.w * b4.w);
        }
}

// ---------------- launch ------------------------------------------------------
extern "C" void kernel_launch(void* const* d_in, const int* in_sizes, int n_in,
                              void* d_out, int out_size) {
    const float* C = (const float*)d_in[0];
    const float* Q = (const float*)d_in[1];
    const float* cmask = (const float*)d_in[2];
    const float* qmask = (const float*)d_in[3];
    const float* w = (const float*)d_in[4];
    float* out = (float*)d_out;

    k0_setup<<<(B * LC + B * LQ) / 256, 256>>>(C, Q, cmask, qmask, w);

    kTR_Ct<<<dim3(LC / 32, D / 32, B), dim3(32, 8)>>>(C);
    kTR_Qt<<<dim3(LQ / 32, D / 32, B), dim3(32, 8)>>>(Q);

    dim3 g1(LQ / 128, LC / 128, B);
    k1_score<<<g1, 256>>>(C, Q, w);

    dim3 g4(LQ / 128, B);
    k4_m<<<g4, 256>>>();

    kTR_Et<<<dim3(LQ / 32, LC / 32, B), dim3(32, 8)>>>();

    dim3 g5(D / 64, LC / 128, B);
    k5_out<<<g5, 256>>>(C, out);
}

// round 15
// speedup vs baseline: 1.1475x; 1.0302x over previous
#include <cuda_runtime.h>
#include <math.h>

#define B    64
#define D    128
#define LC   1024
#define LQ   256
#define NEG_INF -1e30f
#define SA   136     // smem row stride (136%32==8 -> conflict-free fragment reads)
#define SB   72      // smem row stride for 64-wide tiles (72%32==8)

// ---------------- scratch (device globals: no allocation allowed) ----------------
// NOTE: device globals must NEVER be passed as kernel args from host code
// (host shadow symbol + ATS = silent corruption). Bind them in device code only.
__device__ float g_E[(size_t)B * LC * LQ];    // exp(S)  [b][i][j], 64 MiB
__device__ float g_Et[(size_t)B * LQ * LC];   // exp(S)T [b][j][i], 64 MiB
__device__ float g_Ct[(size_t)B * LC * D];    // C^T [b][i][dd], 32 MiB
__device__ float g_Qt[(size_t)B * LQ * D];    // Q^T [b][j][dd], 8 MiB
__device__ float g_M[(size_t)B * LQ * D];     // S2^T @ Ct (already / colsum)
__device__ float g_rowsum[B * LC];
__device__ float g_colsum[B * LQ];
__device__ float g_cw1[B * LC];
__device__ float g_qw2[B * LQ];
__device__ float g_fc[B * LC];
__device__ float g_fq[B * LQ];

// ---------------- tf32 helpers ----------------
__device__ __forceinline__ unsigned f2t(float x) {
    unsigned u; asm("cvt.rna.tf32.f32 %0, %1;" : "=r"(u) : "f"(x)); return u;
}
__device__ __forceinline__ uint4 f2t4(float4 v) {
    return make_uint4(f2t(v.x), f2t(v.y), f2t(v.z), f2t(v.w));
}
__device__ __forceinline__ void mma8(float* c, const unsigned* a, const unsigned* b) {
    asm volatile(
        "mma.sync.aligned.m16n8k8.row.col.f32.tf32.tf32.f32 "
        "{%0,%1,%2,%3},{%4,%5,%6,%7},{%8,%9},{%0,%1,%2,%3};"
        : "+f"(c[0]), "+f"(c[1]), "+f"(c[2]), "+f"(c[3])
        : "r"(a[0]), "r"(a[1]), "r"(a[2]), "r"(a[3]), "r"(b[0]), "r"(b[1]));
}

// ---------------- transpose body: [rows][cols] -> [cols][rows], one batch ----
template<int ROWS, int COLS>
__device__ __forceinline__ void trb(const float* __restrict__ s, float* __restrict__ d) {
    __shared__ float tile[32][33];
    int c0 = blockIdx.x * 32;
    int r0 = blockIdx.y * 32;
    int tx = threadIdx.x, ty = threadIdx.y;
#pragma unroll
    for (int k = 0; k < 32; k += 8)
        tile[ty + k][tx] = s[(size_t)(r0 + ty + k) * COLS + c0 + tx];
    __syncthreads();
#pragma unroll
    for (int k = 0; k < 32; k += 8)
        d[(size_t)(c0 + ty + k) * ROWS + r0 + tx] = tile[tx][ty + k];
}

__global__ void kTR_Ct(const float* __restrict__ C) {
    int b = blockIdx.z;
    trb<D, LC>(C + (size_t)b * D * LC, g_Ct + (size_t)b * LC * D);
}
__global__ void kTR_Qt(const float* __restrict__ Q) {
    int b = blockIdx.z;
    trb<D, LQ>(Q + (size_t)b * D * LQ, g_Qt + (size_t)b * LQ * D);
}

// ---------------- K0: biases, mask factors, zero accumulators ----------------
__global__ void k0_setup(const float* __restrict__ C, const float* __restrict__ Q,
                         const float* __restrict__ cmask, const float* __restrict__ qmask,
                         const float* __restrict__ w) {
    int idx = blockIdx.x * 256 + threadIdx.x;
    if (idx < B * LC) {
        int b = idx >> 10;
        int i = idx & (LC - 1);
        const float* cp = C + (size_t)b * D * LC + i;
        float s = 0.f;
#pragma unroll 4
        for (int dd = 0; dd < D; ++dd) s = fmaf(cp[(size_t)dd * LC], w[dd], s);
        g_cw1[idx] = s;
        g_fc[idx] = __expf((1.0f - cmask[idx]) * NEG_INF);
        g_rowsum[idx] = 0.f;
    } else {
        int t = idx - B * LC;
        if (t < B * LQ) {
            int b = t >> 8;
            int j = t & (LQ - 1);
            const float* qp = Q + (size_t)b * D * LQ + j;
            float s = 0.f;
#pragma unroll 4
            for (int dd = 0; dd < D; ++dd) s = fmaf(qp[(size_t)dd * LQ], w[D + dd], s);
            g_qw2[t] = s;
            g_fq[t] = __expf((1.0f - qmask[t]) * NEG_INF);
            g_colsum[t] = 0.f;
        }
    }
}

// ---------------- K1: E = exp(S) + row/col exp-sums (tf32 MMA) ---------------
// Stores E [i][j] AND Et [j][i], both coalesced via smem transpose.
__global__ __launch_bounds__(256, 2) void k1_score(const float* __restrict__ C,
                                                   const float* __restrict__ Q,
                                                   const float* __restrict__ w) {
    int b = blockIdx.z, i0 = blockIdx.y * 128, j0 = blockIdx.x * 128;

    __shared__ __align__(16) unsigned SMB[2 * 32 * SA];   // As|Bs; reused as tr[64][SA]
    unsigned (*As)[SA] = (unsigned(*)[SA])SMB;
    unsigned (*Bs)[SA] = (unsigned(*)[SA])(SMB + 32 * SA);
    float* tr = (float*)SMB;
    __shared__ float scw[128], sfcs[128], sqw[128], sfqs[128], srow[128], scol[128];

    int tid = threadIdx.x;
    int wid = tid >> 5, lane = tid & 31, g = lane >> 2, t = lane & 3;
    int wm = wid & 3, wn = wid >> 2;     // warp tile: 32(m) x 64(n)

    float acc[2][8][4];
#pragma unroll
    for (int mt = 0; mt < 2; ++mt)
#pragma unroll
        for (int nt = 0; nt < 8; ++nt)
#pragma unroll
            for (int c = 0; c < 4; ++c) acc[mt][nt][c] = 0.f;

    const float* Cb = C + (size_t)b * D * LC;
    const float* Qb = Q + (size_t)b * D * LQ;

    int qm = tid & 31, kr = tid >> 5;    // loader: m-quad, k-row

    uint4 pa[4], pb[4];
#pragma unroll
    for (int p = 0; p < 4; ++p) {        // prefetch chunk 0
        int k = kr + 8 * p;
        float w3 = w[2 * D + k];
        float4 v = *(const float4*)(Cb + (size_t)k * LC + i0 + 4 * qm);
        v.x *= w3; v.y *= w3; v.z *= w3; v.w *= w3;
        pa[p] = f2t4(v);
        pb[p] = f2t4(*(const float4*)(Qb + (size_t)k * LQ + j0 + 4 * qm));
    }

    for (int kc = 0; kc < D; kc += 32) {
        __syncthreads();
#pragma unroll
        for (int p = 0; p < 4; ++p) {
            *(uint4*)&As[kr + 8 * p][4 * qm] = pa[p];
            *(uint4*)&Bs[kr + 8 * p][4 * qm] = pb[p];
        }
        __syncthreads();
        if (kc + 32 < D) {
#pragma unroll
            for (int p = 0; p < 4; ++p) {
                int k = kc + 32 + kr + 8 * p;
                float w3 = w[2 * D + k];
                float4 v = *(const float4*)(Cb + (size_t)k * LC + i0 + 4 * qm);
                v.x *= w3; v.y *= w3; v.z *= w3; v.w *= w3;
                pa[p] = f2t4(v);
                pb[p] = f2t4(*(const float4*)(Qb + (size_t)k * LQ + j0 + 4 * qm));
            }
        }
#pragma unroll
        for (int k8 = 0; k8 < 4; ++k8) {
            int kk = 8 * k8;
            unsigned a[2][4];
#pragma unroll
            for (int mt = 0; mt < 2; ++mt) {
                int R = wm * 32 + mt * 16 + g;
                a[mt][0] = As[kk + t][R];
                a[mt][1] = As[kk + t][R + 8];
                a[mt][2] = As[kk + t + 4][R];
                a[mt][3] = As[kk + t + 4][R + 8];
            }
#pragma unroll
            for (int nt = 0; nt < 8; ++nt) {
                int NN = wn * 64 + nt * 8 + g;
                unsigned bb[2] = { Bs[kk + t][NN], Bs[kk + t + 4][NN] };
#pragma unroll
                for (int mt = 0; mt < 2; ++mt) mma8(acc[mt][nt], a[mt], bb);
            }
        }
    }

    // ---- epilogue: exp into acc, row/col partial sums ----
    __syncthreads();
    if (tid < 128) {
        scw[tid]  = g_cw1[b * LC + i0 + tid];
        sfcs[tid] = g_fc[b * LC + i0 + tid];
        srow[tid] = 0.f;
    } else {
        int j = tid - 128;
        sqw[j]  = g_qw2[b * LQ + j0 + j];
        sfqs[j] = g_fq[b * LQ + j0 + j];
        scol[j] = 0.f;
    }
    __syncthreads();

    float rowp[4] = {0.f, 0.f, 0.f, 0.f};
    float colp[16];
#pragma unroll
    for (int c = 0; c < 16; ++c) colp[c] = 0.f;

#pragma unroll
    for (int mt = 0; mt < 2; ++mt)
#pragma unroll
        for (int half = 0; half < 2; ++half) {
            int rl = wm * 32 + mt * 16 + g + 8 * half;
            float cwv = scw[rl], fcv = sfcs[rl];
#pragma unroll
            for (int nt = 0; nt < 8; ++nt) {
                int cl = wn * 64 + nt * 8 + 2 * t;
                float e0 = __expf(acc[mt][nt][half * 2 + 0] + cwv + sqw[cl]);
                float e1 = __expf(acc[mt][nt][half * 2 + 1] + cwv + sqw[cl + 1]);
                acc[mt][nt][half * 2 + 0] = e0;
                acc[mt][nt][half * 2 + 1] = e1;
                rowp[mt * 2 + half] += e0 * sfqs[cl] + e1 * sfqs[cl + 1];
                colp[nt * 2 + 0] += e0 * fcv;
                colp[nt * 2 + 1] += e1 * fcv;
            }
        }

#pragma unroll
    for (int r = 0; r < 4; ++r) {
        rowp[r] += __shfl_xor_sync(0xffffffffu, rowp[r], 1);
        rowp[r] += __shfl_xor_sync(0xffffffffu, rowp[r], 2);
    }
    if (t == 0) {
#pragma unroll
        for (int mt = 0; mt < 2; ++mt)
#pragma unroll
            for (int half = 0; half < 2; ++half)
                atomicAdd(&srow[wm * 32 + mt * 16 + g + 8 * half], rowp[mt * 2 + half]);
    }
#pragma unroll
    for (int c = 0; c < 16; ++c) {
        colp[c] += __shfl_xor_sync(0xffffffffu, colp[c], 4);
        colp[c] += __shfl_xor_sync(0xffffffffu, colp[c], 8);
        colp[c] += __shfl_xor_sync(0xffffffffu, colp[c], 16);
    }
    if (g == 0) {
#pragma unroll
        for (int nt = 0; nt < 8; ++nt)
#pragma unroll
            for (int par = 0; par < 2; ++par)
                atomicAdd(&scol[wn * 64 + nt * 8 + 2 * t + par], colp[nt * 2 + par]);
    }
    __syncthreads();
    if (tid < 128) atomicAdd(&g_rowsum[b * LC + i0 + tid], srow[tid]);
    else           atomicAdd(&g_colsum[b * LQ + j0 + tid - 128], scol[tid - 128]);

    int r2 = tid >> 4, c16 = tid & 15;

    // ---- coalesced E store [i][j] via smem transpose (2 chunks of 64 i-rows) ----
#pragma unroll
    for (int ch = 0; ch < 2; ++ch) {
        __syncthreads();
        if ((wm >> 1) == ch) {
#pragma unroll
            for (int mt = 0; mt < 2; ++mt)
#pragma unroll
                for (int half = 0; half < 2; ++half) {
                    int rowl = (wm & 1) * 32 + mt * 16 + g + 8 * half;
#pragma unroll
                    for (int nt = 0; nt < 8; ++nt) {
                        int col = wn * 64 + nt * 8 + 2 * t;
                        tr[rowl * SA + col]     = acc[mt][nt][half * 2 + 0];
                        tr[rowl * SA + col + 1] = acc[mt][nt][half * 2 + 1];
                    }
                }
        }
        __syncthreads();
        float* dst = g_E + ((size_t)b * LC + i0 + ch * 64) * LQ + j0;
#pragma unroll
        for (int rr = 0; rr < 4; ++rr)
#pragma unroll
            for (int seg = 0; seg < 2; ++seg) {
                int row = r2 + 16 * rr;
                *(float4*)(dst + (size_t)row * LQ + seg * 64 + 4 * c16) =
                    *(float4*)&tr[row * SA + seg * 64 + 4 * c16];
            }
    }

    // ---- coalesced Et store [j][i] (2 chunks of 64 j-rows) ----
#pragma unroll
    for (int ch = 0; ch < 2; ++ch) {
        __syncthreads();
        if (wn == ch) {
#pragma unroll
            for (int mt = 0; mt < 2; ++mt)
#pragma unroll
                for (int half = 0; half < 2; ++half) {
                    int iil = wm * 32 + mt * 16 + g + 8 * half;
#pragma unroll
                    for (int nt = 0; nt < 8; ++nt) {
                        int jl = nt * 8 + 2 * t;   // local j within 64-chunk
                        tr[jl * SA + iil]       = acc[mt][nt][half * 2 + 0];
                        tr[(jl + 1) * SA + iil] = acc[mt][nt][half * 2 + 1];
                    }
                }
        }
        __syncthreads();
        float* dst = g_Et + ((size_t)b * LQ + j0 + ch * 64) * LC + i0;
#pragma unroll
        for (int rr = 0; rr < 4; ++rr)
#pragma unroll
            for (int seg = 0; seg < 2; ++seg) {
                int row = r2 + 16 * rr;
                *(float4*)(dst + (size_t)row * LC + seg * 64 + 4 * c16) =
                    *(float4*)&tr[row * SA + seg * 64 + 4 * c16];
            }
    }
}

// ---------------- K4: M[j][dd] = (sum_i E[i][j]*fc[i]*Ct[i][dd]) / colsum[j] --
__global__ __launch_bounds__(256, 2) void k4_m() {
    int b = blockIdx.y, j0 = blockIdx.x * 128;

    __shared__ __align__(16) unsigned SMB[2 * 32 * SA];
    unsigned (*As)[SA] = (unsigned(*)[SA])SMB;
    unsigned (*Bs)[SA] = (unsigned(*)[SA])(SMB + 32 * SA);
    float* tr = (float*)SMB;

    int tid = threadIdx.x;
    int wid = tid >> 5, lane = tid & 31, g = lane >> 2, t = lane & 3;
    int wm = wid & 3, wn = wid >> 2;

    float acc[2][8][4];
#pragma unroll
    for (int mt = 0; mt < 2; ++mt)
#pragma unroll
        for (int nt = 0; nt < 8; ++nt)
#pragma unroll
            for (int c = 0; c < 4; ++c) acc[mt][nt][c] = 0.f;

    const float* Eb = g_E + (size_t)b * LC * LQ;
    const float* Ctb = g_Ct + (size_t)b * LC * D;

    int qm = tid & 31, kr = tid >> 5;

    uint4 va[4], vb[4];
#pragma unroll
    for (int p = 0; p < 4; ++p) {
        int i = kr + 8 * p;
        float f = g_fc[b * LC + i];
        float4 v = *(const float4*)(Eb + (size_t)i * LQ + j0 + 4 * qm);
        v.x *= f; v.y *= f; v.z *= f; v.w *= f;
        va[p] = f2t4(v);
        vb[p] = f2t4(*(const float4*)(Ctb + (size_t)i * D + 4 * qm));
    }

    for (int kc = 0; kc < LC; kc += 32) {
        __syncthreads();
#pragma unroll
        for (int p = 0; p < 4; ++p) {
            *(uint4*)&As[kr + 8 * p][4 * qm] = va[p];
            *(uint4*)&Bs[kr + 8 * p][4 * qm] = vb[p];
        }
        __syncthreads();
        if (kc + 32 < LC) {
#pragma unroll
            for (int p = 0; p < 4; ++p) {
                int i = kc + 32 + kr + 8 * p;
                float f = g_fc[b * LC + i];
                float4 v = *(const float4*)(Eb + (size_t)i * LQ + j0 + 4 * qm);
                v.x *= f; v.y *= f; v.z *= f; v.w *= f;
                va[p] = f2t4(v);
                vb[p] = f2t4(*(const float4*)(Ctb + (size_t)i * D + 4 * qm));
            }
        }
#pragma unroll
        for (int k8 = 0; k8 < 4; ++k8) {
            int kk = 8 * k8;
            unsigned a[2][4];
#pragma unroll
            for (int mt = 0; mt < 2; ++mt) {
                int R = wm * 32 + mt * 16 + g;
                a[mt][0] = As[kk + t][R];
                a[mt][1] = As[kk + t][R + 8];
                a[mt][2] = As[kk + t + 4][R];
                a[mt][3] = As[kk + t + 4][R + 8];
            }
#pragma unroll
            for (int nt = 0; nt < 8; ++nt) {
                int NN = wn * 64 + nt * 8 + g;
                unsigned bb[2] = { Bs[kk + t][NN], Bs[kk + t + 4][NN] };
#pragma unroll
                for (int mt = 0; mt < 2; ++mt) mma8(acc[mt][nt], a[mt], bb);
            }
        }
    }

    // ---- coalesced M store via smem transpose (2 chunks of 64 j-rows) ----
    int r2 = tid >> 4, c16 = tid & 15;
#pragma unroll
    for (int ch = 0; ch < 2; ++ch) {
        __syncthreads();
        if ((wm >> 1) == ch) {
#pragma unroll
            for (int mt = 0; mt < 2; ++mt)
#pragma unroll
                for (int half = 0; half < 2; ++half) {
                    int rowl = (wm & 1) * 32 + mt * 16 + g + 8 * half;
                    float ci = 1.0f / g_colsum[b * LQ + j0 + ch * 64 + rowl];
#pragma unroll
                    for (int nt = 0; nt < 8; ++nt) {
                        int col = wn * 64 + nt * 8 + 2 * t;
                        tr[rowl * SA + col]     = acc[mt][nt][half * 2 + 0] * ci;
                        tr[rowl * SA + col + 1] = acc[mt][nt][half * 2 + 1] * ci;
                    }
                }
        }
        __syncthreads();
        float* dst = g_M + ((size_t)b * LQ + j0 + ch * 64) * D;
#pragma unroll
        for (int rr = 0; rr < 4; ++rr)
#pragma unroll
            for (int seg = 0; seg < 2; ++seg) {
                int row = r2 + 16 * rr;
                *(float4*)(dst + (size_t)row * D + seg * 64 + 4 * c16) =
                    *(float4*)&tr[row * SA + seg * 64 + 4 * c16];
            }
    }
}

// ---------------- K5: A & Bmat (dual GEMM) + 4 output channels ----------------
__global__ __launch_bounds__(256, 2) void k5_out(const float* __restrict__ C,
                                                 float* __restrict__ out) {
    int b = blockIdx.z, i0 = blockIdx.y * 128, dd0 = blockIdx.x * 64;

    __shared__ __align__(16) unsigned SMB[32 * SA + 2 * 32 * SB];  // As|Bq|Bm; tr[64][SA]
    unsigned (*As)[SA] = (unsigned(*)[SA])SMB;
    unsigned (*Bq)[SB] = (unsigned(*)[SB])(SMB + 32 * SA);
    unsigned (*Bm)[SB] = (unsigned(*)[SB])(SMB + 32 * SA + 32 * SB);
    float* tr = (float*)SMB;
    __shared__ float sfq[LQ];

    int tid = threadIdx.x;
    int wid = tid >> 5, lane = tid & 31, g = lane >> 2, t = lane & 3;
    int wm = wid & 3, wn = wid >> 2;     // warp tile: 32(m) x 32(n)

    sfq[tid] = g_fq[b * LQ + tid];

    float accA[2][4][4], accB[2][4][4];
#pragma unroll
    for (int mt = 0; mt < 2; ++mt)
#pragma unroll
        for (int nt = 0; nt < 4; ++nt)
#pragma unroll
            for (int c = 0; c < 4; ++c) { accA[mt][nt][c] = 0.f; accB[mt][nt][c] = 0.f; }

    const float* Cb = C + (size_t)b * D * LC;
    const float* Etb = g_Et + (size_t)b * LQ * LC;
    const float* Qtb = g_Qt + (size_t)b * LQ * D;
    const float* Mb = g_M + (size_t)b * LQ * D;

    int qm = tid & 31, kr = tid >> 5;     // A loader (Et rows)
    int qn = tid & 15, krm = tid >> 4;    // Bq/Bm loaders

    float4 ea[4];
    uint4 qa[2], ma[2];
#pragma unroll
    for (int p = 0; p < 4; ++p)
        ea[p] = *(const float4*)(Etb + (size_t)(kr + 8 * p) * LC + i0 + 4 * qm);
#pragma unroll
    for (int p = 0; p < 2; ++p) {
        qa[p] = f2t4(*(const float4*)(Qtb + (size_t)(krm + 16 * p) * D + dd0 + 4 * qn));
        ma[p] = f2t4(*(const float4*)(Mb + (size_t)(krm + 16 * p) * D + dd0 + 4 * qn));
    }

    for (int kc = 0; kc < LQ; kc += 32) {
        __syncthreads();
#pragma unroll
        for (int p = 0; p < 4; ++p) {
            float s = sfq[kc + kr + 8 * p];
            *(uint4*)&As[kr + 8 * p][4 * qm] =
                f2t4(make_float4(ea[p].x * s, ea[p].y * s, ea[p].z * s, ea[p].w * s));
        }
#pragma unroll
        for (int p = 0; p < 2; ++p) {
            *(uint4*)&Bq[krm + 16 * p][4 * qn] = qa[p];
            *(uint4*)&Bm[krm + 16 * p][4 * qn] = ma[p];
        }
        __syncthreads();
        if (kc + 32 < LQ) {
#pragma unroll
            for (int p = 0; p < 4; ++p)
                ea[p] = *(const float4*)(Etb + (size_t)(kc + 32 + kr + 8 * p) * LC + i0 + 4 * qm);
#pragma unroll
            for (int p = 0; p < 2; ++p) {
                qa[p] = f2t4(*(const float4*)(Qtb + (size_t)(kc + 32 + krm + 16 * p) * D + dd0 + 4 * qn));
                ma[p] = f2t4(*(const float4*)(Mb + (size_t)(kc + 32 + krm + 16 * p) * D + dd0 + 4 * qn));
            }
        }
#pragma unroll
        for (int k8 = 0; k8 < 4; ++k8) {
            int kk = 8 * k8;
            unsigned a[2][4];
#pragma unroll
            for (int mt = 0; mt < 2; ++mt) {
                int R = wm * 32 + mt * 16 + g;
                a[mt][0] = As[kk + t][R];
                a[mt][1] = As[kk + t][R + 8];
                a[mt][2] = As[kk + t + 4][R];
                a[mt][3] = As[kk + t + 4][R + 8];
            }
#pragma unroll
            for (int nt = 0; nt < 4; ++nt) {
                int NN = wn * 32 + nt * 8 + g;
                unsigned bq[2] = { Bq[kk + t][NN], Bq[kk + t + 4][NN] };
                unsigned bm[2] = { Bm[kk + t][NN], Bm[kk + t + 4][NN] };
#pragma unroll
                for (int mt = 0; mt < 2; ++mt) {
                    mma8(accA[mt][nt], a[mt], bq);
                    mma8(accB[mt][nt], a[mt], bm);
                }
            }
        }
    }

    // ---- epilogue: rowsum scale, transpose in smem, coalesced stores ----
    float rinv[2][2];
#pragma unroll
    for (int mt = 0; mt < 2; ++mt)
#pragma unroll
        for (int half = 0; half < 2; ++half)
            rinv[mt][half] = 1.0f / g_rowsum[b * LC + i0 + wm * 32 + mt * 16 + g + 8 * half];

    int r2 = tid >> 4, c16 = tid & 15;
    size_t ob = (size_t)b * 4 * D * LC;
    const float* Csrc = Cb + (size_t)dd0 * LC + i0;
    float* o0 = out + ob + (size_t)dd0 * LC + i0;

    // phase A: channels 0 (Ct), 1 (A), 2 (Ct*A)
    __syncthreads();
#pragma unroll
    for (int mt = 0; mt < 2; ++mt)
#pragma unroll
        for (int half = 0; half < 2; ++half) {
            int iil = wm * 32 + mt * 16 + g + 8 * half;
#pragma unroll
            for (int nt = 0; nt < 4; ++nt) {
                int ddl = wn * 32 + nt * 8 + 2 * t;
                tr[ddl * SA + iil]       = accA[mt][nt][half * 2 + 0] * rinv[mt][half];
                tr[(ddl + 1) * SA + iil] = accA[mt][nt][half * 2 + 1] * rinv[mt][half];
            }
        }
    __syncthreads();
#pragma unroll
    for (int rr = 0; rr < 4; ++rr)
#pragma unroll
        for (int seg = 0; seg < 2; ++seg) {
            int row = r2 + 16 * rr;
            int off = seg * 64 + 4 * c16;
            float4 a4 = *(float4*)&tr[row * SA + off];
            float4 c4 = *(const float4*)(Csrc + (size_t)row * LC + off);
            size_t go = (size_t)row * LC + off;
            *(float4*)(o0 + go) = c4;
            *(float4*)(o0 + (size_t)D * LC + go) = a4;
            *(float4*)(o0 + (size_t)2 * D * LC + go) =
                make_float4(c4.x * a4.x, c4.y * a4.y, c4.z * a4.z, c4.w * a4.w);
        }

    // phase B: channel 3 (Ct*Bmat)
    __syncthreads();
#pragma unroll
    for (int mt = 0; mt < 2; ++mt)
#pragma unroll
        for (int half = 0; half < 2; ++half) {
            int iil = wm * 32 + mt * 16 + g + 8 * half;
#pragma unroll
            for (int nt = 0; nt < 4; ++nt) {
                int ddl = wn * 32 + nt * 8 + 2 * t;
                tr[ddl * SA + iil]       = accB[mt][nt][half * 2 + 0] * rinv[mt][half];
                tr[(ddl + 1) * SA + iil] = accB[mt][nt][half * 2 + 1] * rinv[mt][half];
            }
        }
    __syncthreads();
#pragma unroll
    for (int rr = 0; rr < 4; ++rr)
#pragma unroll
        for (int seg = 0; seg < 2; ++seg) {
            int row = r2 + 16 * rr;
            int off = seg * 64 + 4 * c16;
            float4 b4 = *(float4*)&tr[row * SA + off];
            float4 c4 = *(const float4*)(Csrc + (size_t)row * LC + off);
            *(float4*)(o0 + (size_t)3 * D * LC + (size_t)row * LC + off) =
                make_float4(c4.x * b4.x, c4.y * b4.y, c4.z * b4.z, c4.w * b4.w);
        }
}

// ---------------- launch ------------------------------------------------------
extern "C" void kernel_launch(void* const* d_in, const int* in_sizes, int n_in,
                              void* d_out, int out_size) {
    const float* C = (const float*)d_in[0];
    const float* Q = (const float*)d_in[1];
    const float* cmask = (const float*)d_in[2];
    const float* qmask = (const float*)d_in[3];
    const float* w = (const float*)d_in[4];
    float* out = (float*)d_out;

    k0_setup<<<(B * LC + B * LQ) / 256, 256>>>(C, Q, cmask, qmask, w);

    kTR_Ct<<<dim3(LC / 32, D / 32, B), dim3(32, 8)>>>(C);
    kTR_Qt<<<dim3(LQ / 32, D / 32, B), dim3(32, 8)>>>(Q);

    dim3 g1(LQ / 128, LC / 128, B);
    k1_score<<<g1, 256>>>(C, Q, w);

    dim3 g4(LQ / 128, B);
    k4_m<<<g4, 256>>>();

    dim3 g5(D / 64, LC / 128, B);
    k5_out<<<g5, 256>>>(C, out);
}

// round 16
// speedup vs baseline: 1.3999x; 1.2199x over previous
#include <cuda_runtime.h>
#include <cuda_bf16.h>
#include <math.h>

#define B    64
#define D    128
#define LC   1024
#define LQ   256
#define NEG_INF -1e30f
#define SA   136     // smem row stride in 32-bit units (136%32==8 -> conflict-free frags)
#define SB   72      // smem row stride for 64-wide tiles (72%32==8)

// ---------------- scratch (device globals: no allocation allowed) ----------------
// NOTE: device globals must NEVER be passed as kernel args from host code
// (host shadow symbol + ATS = silent corruption). Bind them in device code only.
__device__ float g_E[(size_t)B * LC * LQ];    // exp(S)  [b][i][j], 64 MiB
__device__ float g_Et[(size_t)B * LQ * LC];   // exp(S)T [b][j][i], 64 MiB
__device__ float g_Ct[(size_t)B * LC * D];    // C^T [b][i][dd], 32 MiB
__device__ float g_Qt[(size_t)B * LQ * D];    // Q^T [b][j][dd], 8 MiB
__device__ float g_M[(size_t)B * LQ * D];     // S2^T @ Ct (already / colsum)
__device__ float g_rowsum[B * LC];
__device__ float g_colsum[B * LQ];
__device__ float g_cw1[B * LC];
__device__ float g_qw2[B * LQ];
__device__ float g_fc[B * LC];
__device__ float g_fq[B * LQ];

// ---------------- bf16 helpers ----------------
// pack (even-k, odd-k) fp32 pair into one b32 (lo = even k, hi = odd k)
__device__ __forceinline__ unsigned bfp(float lo, float hi) {
    __nv_bfloat162 h = __floats2bfloat162_rn(lo, hi);
    return *(unsigned*)&h;
}
__device__ __forceinline__ uint4 bfp4(float4 e, float4 o) {
    return make_uint4(bfp(e.x, o.x), bfp(e.y, o.y), bfp(e.z, o.z), bfp(e.w, o.w));
}
// D(16x8) += A(16x16) * B(16x8), bf16 inputs, fp32 accum
__device__ __forceinline__ void mma16(float* c, const unsigned* a, const unsigned* b) {
    asm volatile(
        "mma.sync.aligned.m16n8k16.row.col.f32.bf16.bf16.f32 "
        "{%0,%1,%2,%3},{%4,%5,%6,%7},{%8,%9},{%0,%1,%2,%3};"
        : "+f"(c[0]), "+f"(c[1]), "+f"(c[2]), "+f"(c[3])
        : "r"(a[0]), "r"(a[1]), "r"(a[2]), "r"(a[3]), "r"(b[0]), "r"(b[1]));
}

// ---------------- transpose body: [rows][cols] -> [cols][rows], one batch ----
template<int ROWS, int COLS>
__device__ __forceinline__ void trb(const float* __restrict__ s, float* __restrict__ d) {
    __shared__ float tile[32][33];
    int c0 = blockIdx.x * 32;
    int r0 = blockIdx.y * 32;
    int tx = threadIdx.x, ty = threadIdx.y;
#pragma unroll
    for (int k = 0; k < 32; k += 8)
        tile[ty + k][tx] = s[(size_t)(r0 + ty + k) * COLS + c0 + tx];
    __syncthreads();
#pragma unroll
    for (int k = 0; k < 32; k += 8)
        d[(size_t)(c0 + ty + k) * ROWS + r0 + tx] = tile[tx][ty + k];
}

__global__ void kTR_Ct(const float* __restrict__ C) {
    int b = blockIdx.z;
    trb<D, LC>(C + (size_t)b * D * LC, g_Ct + (size_t)b * LC * D);
}
__global__ void kTR_Qt(const float* __restrict__ Q) {
    int b = blockIdx.z;
    trb<D, LQ>(Q + (size_t)b * D * LQ, g_Qt + (size_t)b * LQ * D);
}

// ---------------- K0: biases, mask factors, zero accumulators ----------------
__global__ void k0_setup(const float* __restrict__ C, const float* __restrict__ Q,
                         const float* __restrict__ cmask, const float* __restrict__ qmask,
                         const float* __restrict__ w) {
    int idx = blockIdx.x * 256 + threadIdx.x;
    if (idx < B * LC) {
        int b = idx >> 10;
        int i = idx & (LC - 1);
        const float* cp = C + (size_t)b * D * LC + i;
        float s = 0.f;
#pragma unroll 4
        for (int dd = 0; dd < D; ++dd) s = fmaf(cp[(size_t)dd * LC], w[dd], s);
        g_cw1[idx] = s;
        g_fc[idx] = __expf((1.0f - cmask[idx]) * NEG_INF);
        g_rowsum[idx] = 0.f;
    } else {
        int t = idx - B * LC;
        if (t < B * LQ) {
            int b = t >> 8;
            int j = t & (LQ - 1);
            const float* qp = Q + (size_t)b * D * LQ + j;
            float s = 0.f;
#pragma unroll 4
            for (int dd = 0; dd < D; ++dd) s = fmaf(qp[(size_t)dd * LQ], w[D + dd], s);
            g_qw2[t] = s;
            g_fq[t] = __expf((1.0f - qmask[t]) * NEG_INF);
            g_colsum[t] = 0.f;
        }
    }
}

// ---------------- K1: E = exp(S) + row/col exp-sums (bf16 MMA) ---------------
// Stores E [i][j] AND Et [j][i], both coalesced via smem transpose.
__global__ __launch_bounds__(256, 2) void k1_score(const float* __restrict__ C,
                                                   const float* __restrict__ Q,
                                                   const float* __restrict__ w) {
    int b = blockIdx.z, i0 = blockIdx.y * 128, j0 = blockIdx.x * 128;

    __shared__ __align__(16) unsigned SMB[2 * 32 * SA];   // tiles; reused as tr[64][SA]
    unsigned (*As2)[SA] = (unsigned(*)[SA])SMB;            // 16 pair-rows x 128 m
    unsigned (*Bs2)[SA] = (unsigned(*)[SA])(SMB + 16 * SA);
    float* tr = (float*)SMB;
    __shared__ float scw[128], sfcs[128], sqw[128], sfqs[128], srow[128], scol[128];

    int tid = threadIdx.x;
    int wid = tid >> 5, lane = tid & 31, g = lane >> 2, t = lane & 3;
    int wm = wid & 3, wn = wid >> 2;     // warp tile: 32(m) x 64(n)

    float acc[2][8][4];
#pragma unroll
    for (int mt = 0; mt < 2; ++mt)
#pragma unroll
        for (int nt = 0; nt < 8; ++nt)
#pragma unroll
            for (int c = 0; c < 4; ++c) acc[mt][nt][c] = 0.f;

    const float* Cb = C + (size_t)b * D * LC;
    const float* Qb = Q + (size_t)b * D * LQ;

    int qm = tid & 31, kr = tid >> 5;    // loader: m-quad, base pair-row (0..7)

    float4 pe[2], po[2], qe[2], qo[2];   // even/odd k rows per slot
#pragma unroll
    for (int p = 0; p < 2; ++p) {        // prefetch chunk 0
        int k0 = 2 * (kr + 8 * p);
        float w3e = w[2 * D + k0], w3o = w[2 * D + k0 + 1];
        float4 ve = *(const float4*)(Cb + (size_t)k0 * LC + i0 + 4 * qm);
        float4 vo = *(const float4*)(Cb + (size_t)(k0 + 1) * LC + i0 + 4 * qm);
        ve.x *= w3e; ve.y *= w3e; ve.z *= w3e; ve.w *= w3e;
        vo.x *= w3o; vo.y *= w3o; vo.z *= w3o; vo.w *= w3o;
        pe[p] = ve; po[p] = vo;
        qe[p] = *(const float4*)(Qb + (size_t)k0 * LQ + j0 + 4 * qm);
        qo[p] = *(const float4*)(Qb + (size_t)(k0 + 1) * LQ + j0 + 4 * qm);
    }

    for (int kc = 0; kc < D; kc += 32) {
        __syncthreads();
#pragma unroll
        for (int p = 0; p < 2; ++p) {
            *(uint4*)&As2[kr + 8 * p][4 * qm] = bfp4(pe[p], po[p]);
            *(uint4*)&Bs2[kr + 8 * p][4 * qm] = bfp4(qe[p], qo[p]);
        }
        __syncthreads();
        if (kc + 32 < D) {
#pragma unroll
            for (int p = 0; p < 2; ++p) {
                int k0 = kc + 32 + 2 * (kr + 8 * p);
                float w3e = w[2 * D + k0], w3o = w[2 * D + k0 + 1];
                float4 ve = *(const float4*)(Cb + (size_t)k0 * LC + i0 + 4 * qm);
                float4 vo = *(const float4*)(Cb + (size_t)(k0 + 1) * LC + i0 + 4 * qm);
                ve.x *= w3e; ve.y *= w3e; ve.z *= w3e; ve.w *= w3e;
                vo.x *= w3o; vo.y *= w3o; vo.z *= w3o; vo.w *= w3o;
                pe[p] = ve; po[p] = vo;
                qe[p] = *(const float4*)(Qb + (size_t)k0 * LQ + j0 + 4 * qm);
                qo[p] = *(const float4*)(Qb + (size_t)(k0 + 1) * LQ + j0 + 4 * qm);
            }
        }
#pragma unroll
        for (int kk2 = 0; kk2 < 16; kk2 += 8) {
            unsigned a[2][4];
#pragma unroll
            for (int mt = 0; mt < 2; ++mt) {
                int R = wm * 32 + mt * 16 + g;
                a[mt][0] = As2[kk2 + t][R];
                a[mt][1] = As2[kk2 + t][R + 8];
                a[mt][2] = As2[kk2 + t + 4][R];
                a[mt][3] = As2[kk2 + t + 4][R + 8];
            }
#pragma unroll
            for (int nt = 0; nt < 8; ++nt) {
                int NN = wn * 64 + nt * 8 + g;
                unsigned bb[2] = { Bs2[kk2 + t][NN], Bs2[kk2 + t + 4][NN] };
#pragma unroll
                for (int mt = 0; mt < 2; ++mt) mma16(acc[mt][nt], a[mt], bb);
            }
        }
    }

    // ---- epilogue: exp into acc, row/col partial sums ----
    __syncthreads();
    if (tid < 128) {
        scw[tid]  = g_cw1[b * LC + i0 + tid];
        sfcs[tid] = g_fc[b * LC + i0 + tid];
        srow[tid] = 0.f;
    } else {
        int j = tid - 128;
        sqw[j]  = g_qw2[b * LQ + j0 + j];
        sfqs[j] = g_fq[b * LQ + j0 + j];
        scol[j] = 0.f;
    }
    __syncthreads();

    float rowp[4] = {0.f, 0.f, 0.f, 0.f};
    float colp[16];
#pragma unroll
    for (int c = 0; c < 16; ++c) colp[c] = 0.f;

#pragma unroll
    for (int mt = 0; mt < 2; ++mt)
#pragma unroll
        for (int half = 0; half < 2; ++half) {
            int rl = wm * 32 + mt * 16 + g + 8 * half;
            float cwv = scw[rl], fcv = sfcs[rl];
#pragma unroll
            for (int nt = 0; nt < 8; ++nt) {
                int cl = wn * 64 + nt * 8 + 2 * t;
                float e0 = __expf(acc[mt][nt][half * 2 + 0] + cwv + sqw[cl]);
                float e1 = __expf(acc[mt][nt][half * 2 + 1] + cwv + sqw[cl + 1]);
                acc[mt][nt][half * 2 + 0] = e0;
                acc[mt][nt][half * 2 + 1] = e1;
                rowp[mt * 2 + half] += e0 * sfqs[cl] + e1 * sfqs[cl + 1];
                colp[nt * 2 + 0] += e0 * fcv;
                colp[nt * 2 + 1] += e1 * fcv;
            }
        }

#pragma unroll
    for (int r = 0; r < 4; ++r) {
        rowp[r] += __shfl_xor_sync(0xffffffffu, rowp[r], 1);
        rowp[r] += __shfl_xor_sync(0xffffffffu, rowp[r], 2);
    }
    if (t == 0) {
#pragma unroll
        for (int mt = 0; mt < 2; ++mt)
#pragma unroll
            for (int half = 0; half < 2; ++half)
                atomicAdd(&srow[wm * 32 + mt * 16 + g + 8 * half], rowp[mt * 2 + half]);
    }
#pragma unroll
    for (int c = 0; c < 16; ++c) {
        colp[c] += __shfl_xor_sync(0xffffffffu, colp[c], 4);
        colp[c] += __shfl_xor_sync(0xffffffffu, colp[c], 8);
        colp[c] += __shfl_xor_sync(0xffffffffu, colp[c], 16);
    }
    if (g == 0) {
#pragma unroll
        for (int nt = 0; nt < 8; ++nt)
#pragma unroll
            for (int par = 0; par < 2; ++par)
                atomicAdd(&scol[wn * 64 + nt * 8 + 2 * t + par], colp[nt * 2 + par]);
    }
    __syncthreads();
    if (tid < 128) atomicAdd(&g_rowsum[b * LC + i0 + tid], srow[tid]);
    else           atomicAdd(&g_colsum[b * LQ + j0 + tid - 128], scol[tid - 128]);

    int r2 = tid >> 4, c16 = tid & 15;

    // ---- coalesced E store [i][j] via smem transpose (2 chunks of 64 i-rows) ----
#pragma unroll
    for (int ch = 0; ch < 2; ++ch) {
        __syncthreads();
        if ((wm >> 1) == ch) {
#pragma unroll
            for (int mt = 0; mt < 2; ++mt)
#pragma unroll
                for (int half = 0; half < 2; ++half) {
                    int rowl = (wm & 1) * 32 + mt * 16 + g + 8 * half;
#pragma unroll
                    for (int nt = 0; nt < 8; ++nt) {
                        int col = wn * 64 + nt * 8 + 2 * t;
                        tr[rowl * SA + col]     = acc[mt][nt][half * 2 + 0];
                        tr[rowl * SA + col + 1] = acc[mt][nt][half * 2 + 1];
                    }
                }
        }
        __syncthreads();
        float* dst = g_E + ((size_t)b * LC + i0 + ch * 64) * LQ + j0;
#pragma unroll
        for (int rr = 0; rr < 4; ++rr)
#pragma unroll
            for (int seg = 0; seg < 2; ++seg) {
                int row = r2 + 16 * rr;
                *(float4*)(dst + (size_t)row * LQ + seg * 64 + 4 * c16) =
                    *(float4*)&tr[row * SA + seg * 64 + 4 * c16];
            }
    }

    // ---- coalesced Et store [j][i] (2 chunks of 64 j-rows) ----
#pragma unroll
    for (int ch = 0; ch < 2; ++ch) {
        __syncthreads();
        if (wn == ch) {
#pragma unroll
            for (int mt = 0; mt < 2; ++mt)
#pragma unroll
                for (int half = 0; half < 2; ++half) {
                    int iil = wm * 32 + mt * 16 + g + 8 * half;
#pragma unroll
                    for (int nt = 0; nt < 8; ++nt) {
                        int jl = nt * 8 + 2 * t;   // local j within 64-chunk
                        tr[jl * SA + iil]       = acc[mt][nt][half * 2 + 0];
                        tr[(jl + 1) * SA + iil] = acc[mt][nt][half * 2 + 1];
                    }
                }
        }
        __syncthreads();
        float* dst = g_Et + ((size_t)b * LQ + j0 + ch * 64) * LC + i0;
#pragma unroll
        for (int rr = 0; rr < 4; ++rr)
#pragma unroll
            for (int seg = 0; seg < 2; ++seg) {
                int row = r2 + 16 * rr;
                *(float4*)(dst + (size_t)row * LC + seg * 64 + 4 * c16) =
                    *(float4*)&tr[row * SA + seg * 64 + 4 * c16];
            }
    }
}

// ---------------- K4: M[j][dd] = (sum_i E[i][j]*fc[i]*Ct[i][dd]) / colsum[j] --
__global__ __launch_bounds__(256, 2) void k4_m() {
    int b = blockIdx.y, j0 = blockIdx.x * 128;

    __shared__ __align__(16) unsigned SMB[2 * 32 * SA];
    unsigned (*As2)[SA] = (unsigned(*)[SA])SMB;
    unsigned (*Bs2)[SA] = (unsigned(*)[SA])(SMB + 16 * SA);
    float* tr = (float*)SMB;

    int tid = threadIdx.x;
    int wid = tid >> 5, lane = tid & 31, g = lane >> 2, t = lane & 3;
    int wm = wid & 3, wn = wid >> 2;

    float acc[2][8][4];
#pragma unroll
    for (int mt = 0; mt < 2; ++mt)
#pragma unroll
        for (int nt = 0; nt < 8; ++nt)
#pragma unroll
            for (int c = 0; c < 4; ++c) acc[mt][nt][c] = 0.f;

    const float* Eb = g_E + (size_t)b * LC * LQ;
    const float* Ctb = g_Ct + (size_t)b * LC * D;

    int qm = tid & 31, kr = tid >> 5;

    float4 ve[2], vo[2], ce[2], co[2];
#pragma unroll
    for (int p = 0; p < 2; ++p) {
        int i0r = 2 * (kr + 8 * p);
        float fe = g_fc[b * LC + i0r], fo = g_fc[b * LC + i0r + 1];
        float4 e = *(const float4*)(Eb + (size_t)i0r * LQ + j0 + 4 * qm);
        float4 o = *(const float4*)(Eb + (size_t)(i0r + 1) * LQ + j0 + 4 * qm);
        e.x *= fe; e.y *= fe; e.z *= fe; e.w *= fe;
        o.x *= fo; o.y *= fo; o.z *= fo; o.w *= fo;
        ve[p] = e; vo[p] = o;
        ce[p] = *(const float4*)(Ctb + (size_t)i0r * D + 4 * qm);
        co[p] = *(const float4*)(Ctb + (size_t)(i0r + 1) * D + 4 * qm);
    }

    for (int kc = 0; kc < LC; kc += 32) {
        __syncthreads();
#pragma unroll
        for (int p = 0; p < 2; ++p) {
            *(uint4*)&As2[kr + 8 * p][4 * qm] = bfp4(ve[p], vo[p]);
            *(uint4*)&Bs2[kr + 8 * p][4 * qm] = bfp4(ce[p], co[p]);
        }
        __syncthreads();
        if (kc + 32 < LC) {
#pragma unroll
            for (int p = 0; p < 2; ++p) {
                int i0r = kc + 32 + 2 * (kr + 8 * p);
                float fe = g_fc[b * LC + i0r], fo = g_fc[b * LC + i0r + 1];
                float4 e = *(const float4*)(Eb + (size_t)i0r * LQ + j0 + 4 * qm);
                float4 o = *(const float4*)(Eb + (size_t)(i0r + 1) * LQ + j0 + 4 * qm);
                e.x *= fe; e.y *= fe; e.z *= fe; e.w *= fe;
                o.x *= fo; o.y *= fo; o.z *= fo; o.w *= fo;
                ve[p] = e; vo[p] = o;
                ce[p] = *(const float4*)(Ctb + (size_t)i0r * D + 4 * qm);
                co[p] = *(const float4*)(Ctb + (size_t)(i0r + 1) * D + 4 * qm);
            }
        }
#pragma unroll
        for (int kk2 = 0; kk2 < 16; kk2 += 8) {
            unsigned a[2][4];
#pragma unroll
            for (int mt = 0; mt < 2; ++mt) {
                int R = wm * 32 + mt * 16 + g;
                a[mt][0] = As2[kk2 + t][R];
                a[mt][1] = As2[kk2 + t][R + 8];
                a[mt][2] = As2[kk2 + t + 4][R];
                a[mt][3] = As2[kk2 + t + 4][R + 8];
            }
#pragma unroll
            for (int nt = 0; nt < 8; ++nt) {
                int NN = wn * 64 + nt * 8 + g;
                unsigned bb[2] = { Bs2[kk2 + t][NN], Bs2[kk2 + t + 4][NN] };
#pragma unroll
                for (int mt = 0; mt < 2; ++mt) mma16(acc[mt][nt], a[mt], bb);
            }
        }
    }

    // ---- coalesced M store via smem transpose (2 chunks of 64 j-rows) ----
    int r2 = tid >> 4, c16 = tid & 15;
#pragma unroll
    for (int ch = 0; ch < 2; ++ch) {
        __syncthreads();
        if ((wm >> 1) == ch) {
#pragma unroll
            for (int mt = 0; mt < 2; ++mt)
#pragma unroll
                for (int half = 0; half < 2; ++half) {
                    int rowl = (wm & 1) * 32 + mt * 16 + g + 8 * half;
                    float ci = 1.0f / g_colsum[b * LQ + j0 + ch * 64 + rowl];
#pragma unroll
                    for (int nt = 0; nt < 8; ++nt) {
                        int col = wn * 64 + nt * 8 + 2 * t;
                        tr[rowl * SA + col]     = acc[mt][nt][half * 2 + 0] * ci;
                        tr[rowl * SA + col + 1] = acc[mt][nt][half * 2 + 1] * ci;
                    }
                }
        }
        __syncthreads();
        float* dst = g_M + ((size_t)b * LQ + j0 + ch * 64) * D;
#pragma unroll
        for (int rr = 0; rr < 4; ++rr)
#pragma unroll
            for (int seg = 0; seg < 2; ++seg) {
                int row = r2 + 16 * rr;
                *(float4*)(dst + (size_t)row * D + seg * 64 + 4 * c16) =
                    *(float4*)&tr[row * SA + seg * 64 + 4 * c16];
            }
    }
}

// ---------------- K5: A & Bmat (dual GEMM) + 4 output channels ----------------
__global__ __launch_bounds__(256, 2) void k5_out(const float* __restrict__ C,
                                                 float* __restrict__ out) {
    int b = blockIdx.z, i0 = blockIdx.y * 128, dd0 = blockIdx.x * 64;

    __shared__ __align__(16) unsigned SMB[32 * SA + 2 * 32 * SB];  // tiles; tr[64][SA]
    unsigned (*As2)[SA] = (unsigned(*)[SA])SMB;                     // 16 x 128
    unsigned (*Bq2)[SB] = (unsigned(*)[SB])(SMB + 16 * SA);         // 16 x 64
    unsigned (*Bm2)[SB] = (unsigned(*)[SB])(SMB + 16 * SA + 16 * SB);
    float* tr = (float*)SMB;
    __shared__ float sfq[LQ];

    int tid = threadIdx.x;
    int wid = tid >> 5, lane = tid & 31, g = lane >> 2, t = lane & 3;
    int wm = wid & 3, wn = wid >> 2;     // warp tile: 32(m) x 32(n)

    sfq[tid] = g_fq[b * LQ + tid];

    float accA[2][4][4], accB[2][4][4];
#pragma unroll
    for (int mt = 0; mt < 2; ++mt)
#pragma unroll
        for (int nt = 0; nt < 4; ++nt)
#pragma unroll
            for (int c = 0; c < 4; ++c) { accA[mt][nt][c] = 0.f; accB[mt][nt][c] = 0.f; }

    const float* Cb = C + (size_t)b * D * LC;
    const float* Etb = g_Et + (size_t)b * LQ * LC;
    const float* Qtb = g_Qt + (size_t)b * LQ * D;
    const float* Mb = g_M + (size_t)b * LQ * D;

    int qm = tid & 31, kr = tid >> 5;     // As loader: m-quad, base pair-row
    int qn = tid & 15, prB = tid >> 4;    // Bq/Bm loader: dd-quad, pair-row (0..15)

    float4 ee[2], eo[2], qge, qgo, mge, mgo;
#pragma unroll
    for (int p = 0; p < 2; ++p) {
        int j0r = 2 * (kr + 8 * p);
        ee[p] = *(const float4*)(Etb + (size_t)j0r * LC + i0 + 4 * qm);
        eo[p] = *(const float4*)(Etb + (size_t)(j0r + 1) * LC + i0 + 4 * qm);
    }
    {
        int j0r = 2 * prB;
        qge = *(const float4*)(Qtb + (size_t)j0r * D + dd0 + 4 * qn);
        qgo = *(const float4*)(Qtb + (size_t)(j0r + 1) * D + dd0 + 4 * qn);
        mge = *(const float4*)(Mb + (size_t)j0r * D + dd0 + 4 * qn);
        mgo = *(const float4*)(Mb + (size_t)(j0r + 1) * D + dd0 + 4 * qn);
    }

    for (int kc = 0; kc < LQ; kc += 32) {
        __syncthreads();
#pragma unroll
        for (int p = 0; p < 2; ++p) {
            int jr = kc + 2 * (kr + 8 * p);
            float se = sfq[jr], so = sfq[jr + 1];
            float4 e = ee[p], o = eo[p];
            e.x *= se; e.y *= se; e.z *= se; e.w *= se;
            o.x *= so; o.y *= so; o.z *= so; o.w *= so;
            *(uint4*)&As2[kr + 8 * p][4 * qm] = bfp4(e, o);
        }
        *(uint4*)&Bq2[prB][4 * qn] = bfp4(qge, qgo);
        *(uint4*)&Bm2[prB][4 * qn] = bfp4(mge, mgo);
        __syncthreads();
        if (kc + 32 < LQ) {
#pragma unroll
            for (int p = 0; p < 2; ++p) {
                int j0r = kc + 32 + 2 * (kr + 8 * p);
                ee[p] = *(const float4*)(Etb + (size_t)j0r * LC + i0 + 4 * qm);
                eo[p] = *(const float4*)(Etb + (size_t)(j0r + 1) * LC + i0 + 4 * qm);
            }
            int j0r = kc + 32 + 2 * prB;
            qge = *(const float4*)(Qtb + (size_t)j0r * D + dd0 + 4 * qn);
            qgo = *(const float4*)(Qtb + (size_t)(j0r + 1) * D + dd0 + 4 * qn);
            mge = *(const float4*)(Mb + (size_t)j0r * D + dd0 + 4 * qn);
            mgo = *(const float4*)(Mb + (size_t)(j0r + 1) * D + dd0 + 4 * qn);
        }
#pragma unroll
        for (int kk2 = 0; kk2 < 16; kk2 += 8) {
            unsigned a[2][4];
#pragma unroll
            for (int mt = 0; mt < 2; ++mt) {
                int R = wm * 32 + mt * 16 + g;
                a[mt][0] = As2[kk2 + t][R];
                a[mt][1] = As2[kk2 + t][R + 8];
                a[mt][2] = As2[kk2 + t + 4][R];
                a[mt][3] = As2[kk2 + t + 4][R + 8];
            }
#pragma unroll
            for (int nt = 0; nt < 4; ++nt) {
                int NN = wn * 32 + nt * 8 + g;
                unsigned bq[2] = { Bq2[kk2 + t][NN], Bq2[kk2 + t + 4][NN] };
                unsigned bm[2] = { Bm2[kk2 + t][NN], Bm2[kk2 + t + 4][NN] };
#pragma unroll
                for (int mt = 0; mt < 2; ++mt) {
                    mma16(accA[mt][nt], a[mt], bq);
                    mma16(accB[mt][nt], a[mt], bm);
                }
            }
        }
    }

    // ---- epilogue: rowsum scale, transpose in smem, coalesced stores ----
    float rinv[2][2];
#pragma unroll
    for (int mt = 0; mt < 2; ++mt)
#pragma unroll
        for (int half = 0; half < 2; ++half)
            rinv[mt][half] = 1.0f / g_rowsum[b * LC + i0 + wm * 32 + mt * 16 + g + 8 * half];

    int r2 = tid >> 4, c16 = tid & 15;
    size_t ob = (size_t)b * 4 * D * LC;
    const float* Csrc = Cb + (size_t)dd0 * LC + i0;
    float* o0 = out + ob + (size_t)dd0 * LC + i0;

    // phase A: channels 0 (Ct), 1 (A), 2 (Ct*A)
    __syncthreads();
#pragma unroll
    for (int mt = 0; mt < 2; ++mt)
#pragma unroll
        for (int half = 0; half < 2; ++half) {
            int iil = wm * 32 + mt * 16 + g + 8 * half;
#pragma unroll
            for (int nt = 0; nt < 4; ++nt) {
                int ddl = wn * 32 + nt * 8 + 2 * t;
                tr[ddl * SA + iil]       = accA[mt][nt][half * 2 + 0] * rinv[mt][half];
                tr[(ddl + 1) * SA + iil] = accA[mt][nt][half * 2 + 1] * rinv[mt][half];
            }
        }
    __syncthreads();
#pragma unroll
    for (int rr = 0; rr < 4; ++rr)
#pragma unroll
        for (int seg = 0; seg < 2; ++seg) {
            int row = r2 + 16 * rr;
            int off = seg * 64 + 4 * c16;
            float4 a4 = *(float4*)&tr[row * SA + off];
            float4 c4 = *(const float4*)(Csrc + (size_t)row * LC + off);
            size_t go = (size_t)row * LC + off;
            *(float4*)(o0 + go) = c4;
            *(float4*)(o0 + (size_t)D * LC + go) = a4;
            *(float4*)(o0 + (size_t)2 * D * LC + go) =
                make_float4(c4.x * a4.x, c4.y * a4.y, c4.z * a4.z, c4.w * a4.w);
        }

    // phase B: channel 3 (Ct*Bmat)
    __syncthreads();
#pragma unroll
    for (int mt = 0; mt < 2; ++mt)
#pragma unroll
        for (int half = 0; half < 2; ++half) {
            int iil = wm * 32 + mt * 16 + g + 8 * half;
#pragma unroll
            for (int nt = 0; nt < 4; ++nt) {
                int ddl = wn * 32 + nt * 8 + 2 * t;
                tr[ddl * SA + iil]       = accB[mt][nt][half * 2 + 0] * rinv[mt][half];
                tr[(ddl + 1) * SA + iil] = accB[mt][nt][half * 2 + 1] * rinv[mt][half];
            }
        }
    __syncthreads();
#pragma unroll
    for (int rr = 0; rr < 4; ++rr)
#pragma unroll
        for (int seg = 0; seg < 2; ++seg) {
            int row = r2 + 16 * rr;
            int off = seg * 64 + 4 * c16;
            float4 b4 = *(float4*)&tr[row * SA + off];
            float4 c4 = *(const float4*)(Csrc + (size_t)row * LC + off);
            *(float4*)(o0 + (size_t)3 * D * LC + (size_t)row * LC + off) =
                make_float4(c4.x * b4.x, c4.y * b4.y, c4.z * b4.z, c4.w * b4.w);
        }
}

// ---------------- launch ------------------------------------------------------
extern "C" void kernel_launch(void* const* d_in, const int* in_sizes, int n_in,
                              void* d_out, int out_size) {
    const float* C = (const float*)d_in[0];
    const float* Q = (const float*)d_in[1];
    const float* cmask = (const float*)d_in[2];
    const float* qmask = (const float*)d_in[3];
    const float* w = (const float*)d_in[4];
    float* out = (float*)d_out;

    k0_setup<<<(B * LC + B * LQ) / 256, 256>>>(C, Q, cmask, qmask, w);

    kTR_Ct<<<dim3(LC / 32, D / 32, B), dim3(32, 8)>>>(C);
    kTR_Qt<<<dim3(LQ / 32, D / 32, B), dim3(32, 8)>>>(Q);

    dim3 g1(LQ / 128, LC / 128, B);
    k1_score<<<g1, 256>>>(C, Q, w);

    dim3 g4(LQ / 128, B);
    k4_m<<<g4, 256>>>();

    dim3 g5(D / 64, LC / 128, B);
    k5_out<<<g5, 256>>>(C, out);
}

// round 17
// speedup vs baseline: 1.6468x; 1.1764x over previous
#include <cuda_runtime.h>
#include <cuda_bf16.h>
#include <math.h>

#define B    64
#define D    128
#define LC   1024
#define LQ   256
#define NEG_INF -1e30f
#define SA   136     // smem row stride in 32-bit units (136%32==8 -> conflict-free frags)
#define SB   72      // smem row stride for 64-wide tiles (72%32==8)

// ---------------- scratch (device globals: no allocation allowed) ----------------
// NOTE: device globals must NEVER be passed as kernel args from host code
// (host shadow symbol + ATS = silent corruption). Bind them in device code only.
// All GEMM operands live in packed bf16x2 form (pairs along the contraction dim).
__device__ unsigned g_Ep [(size_t)B * (LC/2) * LQ];  // (E*fc) pairs along i : k4 A
__device__ unsigned g_Etp[(size_t)B * (LQ/2) * LC];  // (E*fq) pairs along j : k5 A
__device__ unsigned g_Ctp[(size_t)B * (LC/2) * D];   // Ct pairs along i    : k4 B
__device__ unsigned g_Qtp[(size_t)B * (LQ/2) * D];   // Qt pairs along j    : k5 Bq
__device__ unsigned g_Mp [(size_t)B * (LQ/2) * D];   // M  pairs along j    : k5 Bm
__device__ float g_rowsum[B * LC];
__device__ float g_colsum[B * LQ];
__device__ float g_cw1[B * LC];
__device__ float g_qw2[B * LQ];
__device__ float g_fc[B * LC];
__device__ float g_fq[B * LQ];

// ---------------- bf16 helpers ----------------
__device__ __forceinline__ unsigned bfp(float lo, float hi) {
    __nv_bfloat162 h = __floats2bfloat162_rn(lo, hi);
    return *(unsigned*)&h;
}
__device__ __forceinline__ uint4 bfp4(float4 e, float4 o) {
    return make_uint4(bfp(e.x, o.x), bfp(e.y, o.y), bfp(e.z, o.z), bfp(e.w, o.w));
}
// D(16x8) += A(16x16) * B(16x8), bf16 inputs, fp32 accum
__device__ __forceinline__ void mma16(float* c, const unsigned* a, const unsigned* b) {
    asm volatile(
        "mma.sync.aligned.m16n8k16.row.col.f32.bf16.bf16.f32 "
        "{%0,%1,%2,%3},{%4,%5,%6,%7},{%8,%9},{%0,%1,%2,%3};"
        : "+f"(c[0]), "+f"(c[1]), "+f"(c[2]), "+f"(c[3])
        : "r"(a[0]), "r"(a[1]), "r"(a[2]), "r"(a[3]), "r"(b[0]), "r"(b[1]));
}

// ---------------- packed transpose: src [D][COLS] -> dst [COLS/2][D] bf16x2 ---
// dst[c/2][r] = (src[r][c_even], src[r][c_odd])
template<int COLS>
__device__ __forceinline__ void trbp(const float* __restrict__ s, unsigned* __restrict__ d) {
    __shared__ float tile[32][33];
    int c0 = blockIdx.x * 32;   // col base (i or j; contiguous in src)
    int r0 = blockIdx.y * 32;   // dd base
    int tx = threadIdx.x, ty = threadIdx.y;
#pragma unroll
    for (int k = 0; k < 32; k += 8)
        tile[ty + k][tx] = s[(size_t)(r0 + ty + k) * COLS + c0 + tx];
    __syncthreads();
#pragma unroll
    for (int m = 0; m < 2; ++m) {
        int i2l = ty + 8 * m;                        // 0..15
        d[(size_t)(c0 / 2 + i2l) * D + r0 + tx] =
            bfp(tile[tx][2 * i2l], tile[tx][2 * i2l + 1]);
    }
}

__global__ void kTR_Ct(const float* __restrict__ C) {
    int b = blockIdx.z;
    trbp<LC>(C + (size_t)b * D * LC, g_Ctp + (size_t)b * (LC / 2) * D);
}
__global__ void kTR_Qt(const float* __restrict__ Q) {
    int b = blockIdx.z;
    trbp<LQ>(Q + (size_t)b * D * LQ, g_Qtp + (size_t)b * (LQ / 2) * D);
}

// ---------------- K0: biases, mask factors, zero accumulators ----------------
__global__ void k0_setup(const float* __restrict__ C, const float* __restrict__ Q,
                         const float* __restrict__ cmask, const float* __restrict__ qmask,
                         const float* __restrict__ w) {
    int idx = blockIdx.x * 256 + threadIdx.x;
    if (idx < B * LC) {
        int b = idx >> 10;
        int i = idx & (LC - 1);
        const float* cp = C + (size_t)b * D * LC + i;
        float s = 0.f;
#pragma unroll 4
        for (int dd = 0; dd < D; ++dd) s = fmaf(cp[(size_t)dd * LC], w[dd], s);
        g_cw1[idx] = s;
        g_fc[idx] = __expf((1.0f - cmask[idx]) * NEG_INF);
        g_rowsum[idx] = 0.f;
    } else {
        int t = idx - B * LC;
        if (t < B * LQ) {
            int b = t >> 8;
            int j = t & (LQ - 1);
            const float* qp = Q + (size_t)b * D * LQ + j;
            float s = 0.f;
#pragma unroll 4
            for (int dd = 0; dd < D; ++dd) s = fmaf(qp[(size_t)dd * LQ], w[D + dd], s);
            g_qw2[t] = s;
            g_fq[t] = __expf((1.0f - qmask[t]) * NEG_INF);
            g_colsum[t] = 0.f;
        }
    }
}

// ---------------- K1: E = exp(S) + row/col exp-sums (bf16 MMA) ---------------
// Stores Ep (packed along i, *fc) and Etp (packed along j, *fq), both coalesced.
__global__ __launch_bounds__(256, 2) void k1_score(const float* __restrict__ C,
                                                   const float* __restrict__ Q,
                                                   const float* __restrict__ w) {
    int b = blockIdx.z, i0 = blockIdx.y * 128, j0 = blockIdx.x * 128;

    __shared__ __align__(16) unsigned SMB[2 * 32 * SA];   // tiles; reused as tr[64][SA]
    unsigned (*As2)[SA] = (unsigned(*)[SA])SMB;            // 16 pair-rows x 128 m
    unsigned (*Bs2)[SA] = (unsigned(*)[SA])(SMB + 16 * SA);
    float* tr = (float*)SMB;
    __shared__ float scw[128], sfcs[128], sqw[128], sfqs[128], srow[128], scol[128];

    int tid = threadIdx.x;
    int wid = tid >> 5, lane = tid & 31, g = lane >> 2, t = lane & 3;
    int wm = wid & 3, wn = wid >> 2;     // warp tile: 32(m) x 64(n)

    float acc[2][8][4];
#pragma unroll
    for (int mt = 0; mt < 2; ++mt)
#pragma unroll
        for (int nt = 0; nt < 8; ++nt)
#pragma unroll
            for (int c = 0; c < 4; ++c) acc[mt][nt][c] = 0.f;

    const float* Cb = C + (size_t)b * D * LC;
    const float* Qb = Q + (size_t)b * D * LQ;

    int qm = tid & 31, kr = tid >> 5;    // loader: m-quad, base pair-row (0..7)

    float4 pe[2], po[2], qe[2], qo[2];   // even/odd k rows per slot
#pragma unroll
    for (int p = 0; p < 2; ++p) {        // prefetch chunk 0
        int k0 = 2 * (kr + 8 * p);
        float w3e = w[2 * D + k0], w3o = w[2 * D + k0 + 1];
        float4 ve = *(const float4*)(Cb + (size_t)k0 * LC + i0 + 4 * qm);
        float4 vo = *(const float4*)(Cb + (size_t)(k0 + 1) * LC + i0 + 4 * qm);
        ve.x *= w3e; ve.y *= w3e; ve.z *= w3e; ve.w *= w3e;
        vo.x *= w3o; vo.y *= w3o; vo.z *= w3o; vo.w *= w3o;
        pe[p] = ve; po[p] = vo;
        qe[p] = *(const float4*)(Qb + (size_t)k0 * LQ + j0 + 4 * qm);
        qo[p] = *(const float4*)(Qb + (size_t)(k0 + 1) * LQ + j0 + 4 * qm);
    }

    for (int kc = 0; kc < D; kc += 32) {
        __syncthreads();
#pragma unroll
        for (int p = 0; p < 2; ++p) {
            *(uint4*)&As2[kr + 8 * p][4 * qm] = bfp4(pe[p], po[p]);
            *(uint4*)&Bs2[kr + 8 * p][4 * qm] = bfp4(qe[p], qo[p]);
        }
        __syncthreads();
        if (kc + 32 < D) {
#pragma unroll
            for (int p = 0; p < 2; ++p) {
                int k0 = kc + 32 + 2 * (kr + 8 * p);
                float w3e = w[2 * D + k0], w3o = w[2 * D + k0 + 1];
                float4 ve = *(const float4*)(Cb + (size_t)k0 * LC + i0 + 4 * qm);
                float4 vo = *(const float4*)(Cb + (size_t)(k0 + 1) * LC + i0 + 4 * qm);
                ve.x *= w3e; ve.y *= w3e; ve.z *= w3e; ve.w *= w3e;
                vo.x *= w3o; vo.y *= w3o; vo.z *= w3o; vo.w *= w3o;
                pe[p] = ve; po[p] = vo;
                qe[p] = *(const float4*)(Qb + (size_t)k0 * LQ + j0 + 4 * qm);
                qo[p] = *(const float4*)(Qb + (size_t)(k0 + 1) * LQ + j0 + 4 * qm);
            }
        }
#pragma unroll
        for (int kk2 = 0; kk2 < 16; kk2 += 8) {
            unsigned a[2][4];
#pragma unroll
            for (int mt = 0; mt < 2; ++mt) {
                int R = wm * 32 + mt * 16 + g;
                a[mt][0] = As2[kk2 + t][R];
                a[mt][1] = As2[kk2 + t][R + 8];
                a[mt][2] = As2[kk2 + t + 4][R];
                a[mt][3] = As2[kk2 + t + 4][R + 8];
            }
#pragma unroll
            for (int nt = 0; nt < 8; ++nt) {
                int NN = wn * 64 + nt * 8 + g;
                unsigned bb[2] = { Bs2[kk2 + t][NN], Bs2[kk2 + t + 4][NN] };
#pragma unroll
                for (int mt = 0; mt < 2; ++mt) mma16(acc[mt][nt], a[mt], bb);
            }
        }
    }

    // ---- epilogue: exp into acc, row/col partial sums ----
    __syncthreads();
    if (tid < 128) {
        scw[tid]  = g_cw1[b * LC + i0 + tid];
        sfcs[tid] = g_fc[b * LC + i0 + tid];
        srow[tid] = 0.f;
    } else {
        int j = tid - 128;
        sqw[j]  = g_qw2[b * LQ + j0 + j];
        sfqs[j] = g_fq[b * LQ + j0 + j];
        scol[j] = 0.f;
    }
    __syncthreads();

    float rowp[4] = {0.f, 0.f, 0.f, 0.f};
    float colp[16];
#pragma unroll
    for (int c = 0; c < 16; ++c) colp[c] = 0.f;

#pragma unroll
    for (int mt = 0; mt < 2; ++mt)
#pragma unroll
        for (int half = 0; half < 2; ++half) {
            int rl = wm * 32 + mt * 16 + g + 8 * half;
            float cwv = scw[rl], fcv = sfcs[rl];
#pragma unroll
            for (int nt = 0; nt < 8; ++nt) {
                int cl = wn * 64 + nt * 8 + 2 * t;
                float e0 = __expf(acc[mt][nt][half * 2 + 0] + cwv + sqw[cl]);
                float e1 = __expf(acc[mt][nt][half * 2 + 1] + cwv + sqw[cl + 1]);
                acc[mt][nt][half * 2 + 0] = e0;
                acc[mt][nt][half * 2 + 1] = e1;
                rowp[mt * 2 + half] += e0 * sfqs[cl] + e1 * sfqs[cl + 1];
                colp[nt * 2 + 0] += e0 * fcv;
                colp[nt * 2 + 1] += e1 * fcv;
            }
        }

#pragma unroll
    for (int r = 0; r < 4; ++r) {
        rowp[r] += __shfl_xor_sync(0xffffffffu, rowp[r], 1);
        rowp[r] += __shfl_xor_sync(0xffffffffu, rowp[r], 2);
    }
    if (t == 0) {
#pragma unroll
        for (int mt = 0; mt < 2; ++mt)
#pragma unroll
            for (int half = 0; half < 2; ++half)
                atomicAdd(&srow[wm * 32 + mt * 16 + g + 8 * half], rowp[mt * 2 + half]);
    }
#pragma unroll
    for (int c = 0; c < 16; ++c) {
        colp[c] += __shfl_xor_sync(0xffffffffu, colp[c], 4);
        colp[c] += __shfl_xor_sync(0xffffffffu, colp[c], 8);
        colp[c] += __shfl_xor_sync(0xffffffffu, colp[c], 16);
    }
    if (g == 0) {
#pragma unroll
        for (int nt = 0; nt < 8; ++nt)
#pragma unroll
            for (int par = 0; par < 2; ++par)
                atomicAdd(&scol[wn * 64 + nt * 8 + 2 * t + par], colp[nt * 2 + par]);
    }
    __syncthreads();
    if (tid < 128) atomicAdd(&g_rowsum[b * LC + i0 + tid], srow[tid]);
    else           atomicAdd(&g_colsum[b * LQ + j0 + tid - 128], scol[tid - 128]);

    // ---- Ep store: packed along i, premultiplied by fc (2 chunks of 64 i-rows) ----
#pragma unroll
    for (int ch = 0; ch < 2; ++ch) {
        __syncthreads();
        if ((wm >> 1) == ch) {
#pragma unroll
            for (int mt = 0; mt < 2; ++mt)
#pragma unroll
                for (int half = 0; half < 2; ++half) {
                    int rowl = (wm & 1) * 32 + mt * 16 + g + 8 * half;
#pragma unroll
                    for (int nt = 0; nt < 8; ++nt) {
                        int col = wn * 64 + nt * 8 + 2 * t;
                        tr[rowl * SA + col]     = acc[mt][nt][half * 2 + 0];
                        tr[rowl * SA + col + 1] = acc[mt][nt][half * 2 + 1];
                    }
                }
        }
        __syncthreads();
        unsigned* dst = g_Ep + ((size_t)b * (LC / 2) + i0 / 2 + ch * 32) * LQ + j0;
#pragma unroll
        for (int rr = 0; rr < 4; ++rr) {
            int idx = tid + 256 * rr;
            int row = idx >> 5;          // 0..31 pair-row
            int c4 = idx & 31;           // 0..31 (x4 -> 0..124)
            float fce = sfcs[ch * 64 + 2 * row], fco = sfcs[ch * 64 + 2 * row + 1];
            float4 e = *(float4*)&tr[(2 * row) * SA + 4 * c4];
            float4 o = *(float4*)&tr[(2 * row + 1) * SA + 4 * c4];
            e.x *= fce; e.y *= fce; e.z *= fce; e.w *= fce;
            o.x *= fco; o.y *= fco; o.z *= fco; o.w *= fco;
            *(uint4*)(dst + (size_t)row * LQ + 4 * c4) = bfp4(e, o);
        }
    }

    // ---- Etp store: packed along j, premultiplied by fq (2 chunks of 64 j-rows) ----
#pragma unroll
    for (int ch = 0; ch < 2; ++ch) {
        __syncthreads();
        if (wn == ch) {
#pragma unroll
            for (int mt = 0; mt < 2; ++mt)
#pragma unroll
                for (int half = 0; half < 2; ++half) {
                    int iil = wm * 32 + mt * 16 + g + 8 * half;
#pragma unroll
                    for (int nt = 0; nt < 8; ++nt) {
                        int jl = nt * 8 + 2 * t;   // local j within 64-chunk
                        tr[jl * SA + iil]       = acc[mt][nt][half * 2 + 0];
                        tr[(jl + 1) * SA + iil] = acc[mt][nt][half * 2 + 1];
                    }
                }
        }
        __syncthreads();
        unsigned* dst = g_Etp + ((size_t)b * (LQ / 2) + j0 / 2 + ch * 32) * LC + i0;
#pragma unroll
        for (int rr = 0; rr < 4; ++rr) {
            int idx = tid + 256 * rr;
            int row = idx >> 5;          // 0..31 pair-row (j2 local)
            int c4 = idx & 31;
            float fqe = sfqs[ch * 64 + 2 * row], fqo = sfqs[ch * 64 + 2 * row + 1];
            float4 e = *(float4*)&tr[(2 * row) * SA + 4 * c4];
            float4 o = *(float4*)&tr[(2 * row + 1) * SA + 4 * c4];
            e.x *= fqe; e.y *= fqe; e.z *= fqe; e.w *= fqe;
            o.x *= fqo; o.y *= fqo; o.z *= fqo; o.w *= fqo;
            *(uint4*)(dst + (size_t)row * LC + 4 * c4) = bfp4(e, o);
        }
    }
}

// ---------------- K4: M[j][dd] = (sum_i Ep*Ctp) / colsum[j]  -> g_Mp ---------
__global__ __launch_bounds__(256, 2) void k4_m() {
    int b = blockIdx.y, j0 = blockIdx.x * 128;

    __shared__ __align__(16) unsigned SMB[2 * 32 * SA];
    unsigned (*As2)[SA] = (unsigned(*)[SA])SMB;
    unsigned (*Bs2)[SA] = (unsigned(*)[SA])(SMB + 16 * SA);
    float* tr = (float*)SMB;

    int tid = threadIdx.x;
    int wid = tid >> 5, lane = tid & 31, g = lane >> 2, t = lane & 3;
    int wm = wid & 3, wn = wid >> 2;

    float acc[2][8][4];
#pragma unroll
    for (int mt = 0; mt < 2; ++mt)
#pragma unroll
        for (int nt = 0; nt < 8; ++nt)
#pragma unroll
            for (int c = 0; c < 4; ++c) acc[mt][nt][c] = 0.f;

    const unsigned* Epb = g_Ep + (size_t)b * (LC / 2) * LQ;
    const unsigned* Ctpb = g_Ctp + (size_t)b * (LC / 2) * D;

    uint4 va[2], vb[2];
#pragma unroll
    for (int p = 0; p < 2; ++p) {
        int idx = tid + 256 * p;
        int r = idx >> 5, c4 = idx & 31;
        va[p] = *(const uint4*)(Epb + (size_t)r * LQ + j0 + 4 * c4);
        vb[p] = *(const uint4*)(Ctpb + (size_t)r * D + 4 * c4);
    }

    for (int kc2 = 0; kc2 < LC / 2; kc2 += 16) {
        __syncthreads();
#pragma unroll
        for (int p = 0; p < 2; ++p) {
            int idx = tid + 256 * p;
            int r = idx >> 5, c4 = idx & 31;
            *(uint4*)&As2[r][4 * c4] = va[p];
            *(uint4*)&Bs2[r][4 * c4] = vb[p];
        }
        __syncthreads();
        if (kc2 + 16 < LC / 2) {
#pragma unroll
            for (int p = 0; p < 2; ++p) {
                int idx = tid + 256 * p;
                int r = kc2 + 16 + (idx >> 5), c4 = idx & 31;
                va[p] = *(const uint4*)(Epb + (size_t)r * LQ + j0 + 4 * c4);
                vb[p] = *(const uint4*)(Ctpb + (size_t)r * D + 4 * c4);
            }
        }
#pragma unroll
        for (int kk2 = 0; kk2 < 16; kk2 += 8) {
            unsigned a[2][4];
#pragma unroll
            for (int mt = 0; mt < 2; ++mt) {
                int R = wm * 32 + mt * 16 + g;
                a[mt][0] = As2[kk2 + t][R];
                a[mt][1] = As2[kk2 + t][R + 8];
                a[mt][2] = As2[kk2 + t + 4][R];
                a[mt][3] = As2[kk2 + t + 4][R + 8];
            }
#pragma unroll
            for (int nt = 0; nt < 8; ++nt) {
                int NN = wn * 64 + nt * 8 + g;
                unsigned bb[2] = { Bs2[kk2 + t][NN], Bs2[kk2 + t + 4][NN] };
#pragma unroll
                for (int mt = 0; mt < 2; ++mt) mma16(acc[mt][nt], a[mt], bb);
            }
        }
    }

    // ---- Mp store: divide by colsum, pack pairs along j (2 chunks of 64 j-rows) ----
#pragma unroll
    for (int ch = 0; ch < 2; ++ch) {
        __syncthreads();
        if ((wm >> 1) == ch) {
#pragma unroll
            for (int mt = 0; mt < 2; ++mt)
#pragma unroll
                for (int half = 0; half < 2; ++half) {
                    int rowl = (wm & 1) * 32 + mt * 16 + g + 8 * half;
                    float ci = 1.0f / g_colsum[b * LQ + j0 + ch * 64 + rowl];
#pragma unroll
                    for (int nt = 0; nt < 8; ++nt) {
                        int col = wn * 64 + nt * 8 + 2 * t;
                        tr[rowl * SA + col]     = acc[mt][nt][half * 2 + 0] * ci;
                        tr[rowl * SA + col + 1] = acc[mt][nt][half * 2 + 1] * ci;
                    }
                }
        }
        __syncthreads();
        unsigned* dst = g_Mp + ((size_t)b * (LQ / 2) + (j0 + ch * 64) / 2) * D;
#pragma unroll
        for (int rr = 0; rr < 4; ++rr) {
            int idx = tid + 256 * rr;
            int row = idx >> 5;          // 0..31 pair-row
            int c4 = idx & 31;
            float4 e = *(float4*)&tr[(2 * row) * SA + 4 * c4];
            float4 o = *(float4*)&tr[(2 * row + 1) * SA + 4 * c4];
            *(uint4*)(dst + (size_t)row * D + 4 * c4) = bfp4(e, o);
        }
    }
}

// ---------------- K5: A & Bmat (dual GEMM) + 4 output channels ----------------
__global__ __launch_bounds__(256, 2) void k5_out(const float* __restrict__ C,
                                                 float* __restrict__ out) {
    int b = blockIdx.z, i0 = blockIdx.y * 128, dd0 = blockIdx.x * 64;

    __shared__ __align__(16) unsigned SMB[32 * SA + 2 * 32 * SB];  // tiles; tr[64][SA]
    unsigned (*As2)[SA] = (unsigned(*)[SA])SMB;                     // 16 x 128
    unsigned (*Bq2)[SB] = (unsigned(*)[SB])(SMB + 16 * SA);         // 16 x 64
    unsigned (*Bm2)[SB] = (unsigned(*)[SB])(SMB + 16 * SA + 16 * SB);
    float* tr = (float*)SMB;

    int tid = threadIdx.x;
    int wid = tid >> 5, lane = tid & 31, g = lane >> 2, t = lane & 3;
    int wm = wid & 3, wn = wid >> 2;     // warp tile: 32(m) x 32(n)

    float accA[2][4][4], accB[2][4][4];
#pragma unroll
    for (int mt = 0; mt < 2; ++mt)
#pragma unroll
        for (int nt = 0; nt < 4; ++nt)
#pragma unroll
            for (int c = 0; c < 4; ++c) { accA[mt][nt][c] = 0.f; accB[mt][nt][c] = 0.f; }

    const float* Cb = C + (size_t)b * D * LC;
    const unsigned* Etpb = g_Etp + (size_t)b * (LQ / 2) * LC;
    const unsigned* Qtpb = g_Qtp + (size_t)b * (LQ / 2) * D;
    const unsigned* Mpb = g_Mp + (size_t)b * (LQ / 2) * D;

    int rB = tid >> 4, c4B = tid & 15;   // B loaders: 16 x 16 uint4

    uint4 ea[2], qa, ma;
#pragma unroll
    for (int p = 0; p < 2; ++p) {
        int idx = tid + 256 * p;
        int r = idx >> 5, c4 = idx & 31;
        ea[p] = *(const uint4*)(Etpb + (size_t)r * LC + i0 + 4 * c4);
    }
    qa = *(const uint4*)(Qtpb + (size_t)rB * D + dd0 + 4 * c4B);
    ma = *(const uint4*)(Mpb + (size_t)rB * D + dd0 + 4 * c4B);

    for (int kc2 = 0; kc2 < LQ / 2; kc2 += 16) {
        __syncthreads();
#pragma unroll
        for (int p = 0; p < 2; ++p) {
            int idx = tid + 256 * p;
            int r = idx >> 5, c4 = idx & 31;
            *(uint4*)&As2[r][4 * c4] = ea[p];
        }
        *(uint4*)&Bq2[rB][4 * c4B] = qa;
        *(uint4*)&Bm2[rB][4 * c4B] = ma;
        __syncthreads();
        if (kc2 + 16 < LQ / 2) {
#pragma unroll
            for (int p = 0; p < 2; ++p) {
                int idx = tid + 256 * p;
                int r = kc2 + 16 + (idx >> 5), c4 = idx & 31;
                ea[p] = *(const uint4*)(Etpb + (size_t)r * LC + i0 + 4 * c4);
            }
            qa = *(const uint4*)(Qtpb + (size_t)(kc2 + 16 + rB) * D + dd0 + 4 * c4B);
            ma = *(const uint4*)(Mpb + (size_t)(kc2 + 16 + rB) * D + dd0 + 4 * c4B);
        }
#pragma unroll
        for (int kk2 = 0; kk2 < 16; kk2 += 8) {
            unsigned a[2][4];
#pragma unroll
            for (int mt = 0; mt < 2; ++mt) {
                int R = wm * 32 + mt * 16 + g;
                a[mt][0] = As2[kk2 + t][R];
                a[mt][1] = As2[kk2 + t][R + 8];
                a[mt][2] = As2[kk2 + t + 4][R];
                a[mt][3] = As2[kk2 + t + 4][R + 8];
            }
#pragma unroll
            for (int nt = 0; nt < 4; ++nt) {
                int NN = wn * 32 + nt * 8 + g;
                unsigned bq[2] = { Bq2[kk2 + t][NN], Bq2[kk2 + t + 4][NN] };
                unsigned bm[2] = { Bm2[kk2 + t][NN], Bm2[kk2 + t + 4][NN] };
#pragma unroll
                for (int mt = 0; mt < 2; ++mt) {
                    mma16(accA[mt][nt], a[mt], bq);
                    mma16(accB[mt][nt], a[mt], bm);
                }
            }
        }
    }

    // ---- epilogue: rowsum scale, transpose in smem, coalesced stores ----
    float rinv[2][2];
#pragma unroll
    for (int mt = 0; mt < 2; ++mt)
#pragma unroll
        for (int half = 0; half < 2; ++half)
            rinv[mt][half] = 1.0f / g_rowsum[b * LC + i0 + wm * 32 + mt * 16 + g + 8 * half];

    int r2 = tid >> 4, c16 = tid & 15;
    size_t ob = (size_t)b * 4 * D * LC;
    const float* Csrc = Cb + (size_t)dd0 * LC + i0;
    float* o0 = out + ob + (size_t)dd0 * LC + i0;

    // phase A: channels 0 (Ct), 1 (A), 2 (Ct*A)
    __syncthreads();
#pragma unroll
    for (int mt = 0; mt < 2; ++mt)
#pragma unroll
        for (int half = 0; half < 2; ++half) {
            int iil = wm * 32 + mt * 16 + g + 8 * half;
#pragma unroll
            for (int nt = 0; nt < 4; ++nt) {
                int ddl = wn * 32 + nt * 8 + 2 * t;
                tr[ddl * SA + iil]       = accA[mt][nt][half * 2 + 0] * rinv[mt][half];
                tr[(ddl + 1) * SA + iil] = accA[mt][nt][half * 2 + 1] * rinv[mt][half];
            }
        }
    __syncthreads();
#pragma unroll
    for (int rr = 0; rr < 4; ++rr)
#pragma unroll
        for (int seg = 0; seg < 2; ++seg) {
            int row = r2 + 16 * rr;
            int off = seg * 64 + 4 * c16;
            float4 a4 = *(float4*)&tr[row * SA + off];
            float4 c4 = *(const float4*)(Csrc + (size_t)row * LC + off);
            size_t go = (size_t)row * LC + off;
            *(float4*)(o0 + go) = c4;
            *(float4*)(o0 + (size_t)D * LC + go) = a4;
            *(float4*)(o0 + (size_t)2 * D * LC + go) =
                make_float4(c4.x * a4.x, c4.y * a4.y, c4.z * a4.z, c4.w * a4.w);
        }

    // phase B: channel 3 (Ct*Bmat)
    __syncthreads();
#pragma unroll
    for (int mt = 0; mt < 2; ++mt)
#pragma unroll
        for (int half = 0; half < 2; ++half) {
            int iil = wm * 32 + mt * 16 + g + 8 * half;
#pragma unroll
            for (int nt = 0; nt < 4; ++nt) {
                int ddl = wn * 32 + nt * 8 + 2 * t;
                tr[ddl * SA + iil]       = accB[mt][nt][half * 2 + 0] * rinv[mt][half];
                tr[(ddl + 1) * SA + iil] = accB[mt][nt][half * 2 + 1] * rinv[mt][half];
            }
        }
    __syncthreads();
#pragma unroll
    for (int rr = 0; rr < 4; ++rr)
#pragma unroll
        for (int seg = 0; seg < 2; ++seg) {
            int row = r2 + 16 * rr;
            int off = seg * 64 + 4 * c16;
            float4 b4 = *(float4*)&tr[row * SA + off];
            float4 c4 = *(const float4*)(Csrc + (size_t)row * LC + off);
            *(float4*)(o0 + (size_t)3 * D * LC + (size_t)row * LC + off) =
                make_float4(c4.x * b4.x, c4.y * b4.y, c4.z * b4.z, c4.w * b4.w);
        }
}

// ---------------- launch ------------------------------------------------------
extern "C" void kernel_launch(void* const* d_in, const int* in_sizes, int n_in,
                              void* d_out, int out_size) {
    const float* C = (const float*)d_in[0];
    const float* Q = (const float*)d_in[1];
    const float* cmask = (const float*)d_in[2];
    const float* qmask = (const float*)d_in[3];
    const float* w = (const float*)d_in[4];
    float* out = (float*)d_out;

    k0_setup<<<(B * LC + B * LQ) / 256, 256>>>(C, Q, cmask, qmask, w);

    kTR_Ct<<<dim3(LC / 32, D / 32, B), dim3(32, 8)>>>(C);
    kTR_Qt<<<dim3(LQ / 32, D / 32, B), dim3(32, 8)>>>(Q);

    dim3 g1(LQ / 128, LC / 128, B);
    k1_score<<<g1, 256>>>(C, Q, w);

    dim3 g4(LQ / 128, B);
    k4_m<<<g4, 256>>>();

    dim3 g5(D / 64, LC / 128, B);
    k5_out<<<g5, 256>>>(C, out);
}